// round 12
// baseline (speedup 1.0000x reference)
#include <cuda_runtime.h>
#include <cuda_bf16.h>
#include <math.h>
#include <stdint.h>

// Problem constants
static constexpr int T_   = 512;
static constexpr int B_   = 32;
static constexpr int H_   = 1024;
static constexpr int G4_  = 4096;   // 4*H
static constexpr int NL_  = 5;
static constexpr int NBLK = 128;    // persistent grid size

// ---------------- scratch (device globals; no allocations allowed) ----------
__device__ float g_seq0[(size_t)T_ * B_ * H_];
__device__ float g_seq1[(size_t)T_ * B_ * H_];
__device__ float g_gates[(size_t)T_ * B_ * G4_];
__device__ float g_h0[B_ * H_];                   // final h (for head)
// two-level barrier state (all stay 0 between launches/replays)
__device__ unsigned int g_cnt8[8 * 32];           // group counters, 128B apart
__device__ unsigned int g_root = 0;
__device__ unsigned int g_gen  = 0;
// split-bf16 operands (input GEMM)
__device__ __nv_bfloat16 g_Ah[(size_t)T_ * B_ * H_];
__device__ __nv_bfloat16 g_Al[(size_t)T_ * B_ * H_];
__device__ __nv_bfloat16 g_Wh[(size_t)2 * G4_ * H_];
__device__ __nv_bfloat16 g_Wl[(size_t)2 * G4_ * H_];
// split-bf16 recurrent weights
__device__ __nv_bfloat16 g_WhH[(size_t)2 * G4_ * H_];
__device__ __nv_bfloat16 g_WhL[(size_t)2 * G4_ * H_];
// double-buffered bf16 hidden state (hi/lo), [B][H] row-major
__device__ __nv_bfloat16 g_hhA[B_ * H_];
__device__ __nv_bfloat16 g_hlA[B_ * H_];
__device__ __nv_bfloat16 g_hhB[B_ * H_];
__device__ __nv_bfloat16 g_hlB[B_ * H_];

__device__ __forceinline__ uint32_t smem_u32(const void* p) {
    uint32_t a;
    asm("{ .reg .u64 t; cvta.to.shared.u64 t, %1; cvt.u32.u64 %0, t; }" : "=r"(a) : "l"(p));
    return a;
}

__device__ __forceinline__ void mma16816(float* c, const uint32_t* a, const uint32_t* b) {
    asm volatile(
        "mma.sync.aligned.m16n8k16.row.col.f32.bf16.bf16.f32 "
        "{%0,%1,%2,%3}, {%4,%5,%6,%7}, {%8,%9}, {%0,%1,%2,%3};"
        : "+f"(c[0]), "+f"(c[1]), "+f"(c[2]), "+f"(c[3])
        : "r"(a[0]), "r"(a[1]), "r"(a[2]), "r"(a[3]), "r"(b[0]), "r"(b[1]));
}
__device__ __forceinline__ void ldmx4(uint32_t* r, uint32_t addr) {
    asm volatile("ldmatrix.sync.aligned.m8n8.x4.shared.b16 {%0,%1,%2,%3}, [%4];"
                 : "=r"(r[0]), "=r"(r[1]), "=r"(r[2]), "=r"(r[3]) : "r"(addr));
}
__device__ __forceinline__ void ldmx2(uint32_t* r, uint32_t addr) {
    asm volatile("ldmatrix.sync.aligned.m8n8.x2.shared.b16 {%0,%1}, [%2];"
                 : "=r"(r[0]), "=r"(r[1]) : "r"(addr));
}

// ---------------- embedding gather ------------------------------------------
__global__ void embed_k(const int* __restrict__ x, const float* __restrict__ emb) {
    int tb = blockIdx.x;
    int t = tb / B_;
    int b = tb % B_;
    int tok = x[b * T_ + t];
    const float4* src = (const float4*)(emb + (size_t)tok * H_);
    float4* dst = (float4*)(g_seq0 + (size_t)tb * H_);
    dst[threadIdx.x] = src[threadIdx.x];
}

// ---------------- fp32 -> bf16 (hi, lo) split -------------------------------
__global__ void split_bf16_k(const float* __restrict__ src,
                             __nv_bfloat16* __restrict__ hi,
                             __nv_bfloat16* __restrict__ lo, int n4) {
    int i = blockIdx.x * blockDim.x + threadIdx.x;
    if (i >= n4) return;
    float4 v = ((const float4*)src)[i];
    __nv_bfloat16 h0 = __float2bfloat16(v.x);
    __nv_bfloat16 h1 = __float2bfloat16(v.y);
    __nv_bfloat16 h2 = __float2bfloat16(v.z);
    __nv_bfloat16 h3 = __float2bfloat16(v.w);
    __nv_bfloat16 l0 = __float2bfloat16(v.x - __bfloat162float(h0));
    __nv_bfloat16 l1 = __float2bfloat16(v.y - __bfloat162float(h1));
    __nv_bfloat16 l2 = __float2bfloat16(v.z - __bfloat162float(h2));
    __nv_bfloat16 l3 = __float2bfloat16(v.w - __bfloat162float(h3));
    __nv_bfloat162* hp = (__nv_bfloat162*)hi;
    __nv_bfloat162* lp = (__nv_bfloat162*)lo;
    hp[2 * i]     = __nv_bfloat162(h0, h1);
    hp[2 * i + 1] = __nv_bfloat162(h2, h3);
    lp[2 * i]     = __nv_bfloat162(l0, l1);
    lp[2 * i + 1] = __nv_bfloat162(l2, l3);
}

// ---------------- mma.sync split-bf16 input GEMM (double-buffered) ----------
// C[16384,4096] = A[16384,1024] @ W[4096,1024]^T + bias, via 3 bf16 products.
// Block tile 128x128, BK=64, 8 warps (2m x 4n). Two-stage smem, 1 sync/iter.
// Dynamic smem layout: As0 @0, As1 @16384, Ws0 @32768, Ws1 @49152 (64 KB).
static constexpr int GEMM_SMEM = 65536;

__global__ __launch_bounds__(256, 2)
void gemm_mma_k(const __nv_bfloat16* __restrict__ Ah, const __nv_bfloat16* __restrict__ Al,
                const __nv_bfloat16* __restrict__ Wh, const __nv_bfloat16* __restrict__ Wl,
                const float* __restrict__ bias, float* __restrict__ C) {
    extern __shared__ char gsm[];

    const int tid  = threadIdx.x;
    const int warp = tid >> 5;
    const int lane = tid & 31;
    const int wm = warp >> 2;
    const int wn = warp & 3;
    const int m0 = blockIdx.y * 128;
    const int n0 = blockIdx.x * 128;

    const __nv_bfloat16* srcA[3] = {Ah, Ah, Al};
    const __nv_bfloat16* srcW[3] = {Wh, Wl, Wh};

    int rowL[4], uL[4], dstL[4];
#pragma unroll
    for (int i = 0; i < 4; i++) {
        int idx = i * 256 + tid;
        rowL[i] = idx >> 3;
        uL[i]   = idx & 7;
        dstL[i] = (rowL[i] * 64 + ((uL[i] ^ (rowL[i] & 7)) << 3)) * 2;   // bytes
    }

    float acc[4][4][4];
#pragma unroll
    for (int mt = 0; mt < 4; mt++)
#pragma unroll
        for (int nt = 0; nt < 4; nt++)
#pragma unroll
            for (int q = 0; q < 4; q++) acc[mt][nt][q] = 0.f;

    int lrowA[4], lrowB[4];
#pragma unroll
    for (int mt = 0; mt < 4; mt++) lrowA[mt] = wm * 64 + mt * 16 + (lane & 15);
#pragma unroll
    for (int nt = 0; nt < 4; nt++) lrowB[nt] = wn * 32 + nt * 8 + (lane & 7);
    const uint32_t sbase = smem_u32(gsm);

    float4 pa[4], pw[4];
#pragma unroll
    for (int i = 0; i < 4; i++) {
        pa[i] = *(const float4*)(srcA[0] + (size_t)(m0 + rowL[i]) * H_ + uL[i] * 8);
        pw[i] = *(const float4*)(srcW[0] + (size_t)(n0 + rowL[i]) * H_ + uL[i] * 8);
    }
    // fill stage 0
#pragma unroll
    for (int i = 0; i < 4; i++) {
        *(float4*)(gsm + dstL[i])         = pa[i];
        *(float4*)(gsm + 32768 + dstL[i]) = pw[i];
    }
    __syncthreads();

    for (int it = 0; it < 48; it++) {
        const int cur = it & 1;
        const int nxt = cur ^ 1;
        const uint32_t a_base = sbase + cur * 16384;
        const uint32_t w_base = sbase + 32768 + cur * 16384;

        // prefetch next tile into registers (global loads fly over the MMAs)
        if (it + 1 < 48) {
            int p2 = (it + 1) >> 4;
            int kcol2 = ((it + 1) & 15) * 64;
#pragma unroll
            for (int i = 0; i < 4; i++) {
                pa[i] = *(const float4*)(srcA[p2] + (size_t)(m0 + rowL[i]) * H_ + kcol2 + uL[i] * 8);
                pw[i] = *(const float4*)(srcW[p2] + (size_t)(n0 + rowL[i]) * H_ + kcol2 + uL[i] * 8);
            }
        }

#pragma unroll
        for (int ks = 0; ks < 4; ks++) {
            uint32_t af[4][4], bf[4][2];
            int ua = ks * 2 + (lane >> 4);
#pragma unroll
            for (int mt = 0; mt < 4; mt++)
                ldmx4(af[mt], a_base + (uint32_t)(lrowA[mt] * 128 + ((ua ^ (lrowA[mt] & 7)) << 4)));
            int ub = ks * 2 + ((lane >> 3) & 1);
#pragma unroll
            for (int nt = 0; nt < 4; nt++)
                ldmx2(bf[nt], w_base + (uint32_t)(lrowB[nt] * 128 + ((ub ^ (lrowB[nt] & 7)) << 4)));
#pragma unroll
            for (int mt = 0; mt < 4; mt++)
#pragma unroll
                for (int nt = 0; nt < 4; nt++)
                    mma16816(acc[mt][nt], af[mt], bf[nt]);
        }

        // store prefetched tile into the other stage
        if (it + 1 < 48) {
#pragma unroll
            for (int i = 0; i < 4; i++) {
                *(float4*)(gsm + nxt * 16384 + dstL[i])         = pa[i];
                *(float4*)(gsm + 32768 + nxt * 16384 + dstL[i]) = pw[i];
            }
        }
        __syncthreads();
    }

    const int qr = lane >> 2;
    const int qc = (lane & 3) * 2;
#pragma unroll
    for (int mt = 0; mt < 4; mt++) {
        int rm = m0 + wm * 64 + mt * 16 + qr;
#pragma unroll
        for (int nt = 0; nt < 4; nt++) {
            int cb = n0 + wn * 32 + nt * 8 + qc;
            float b0 = bias[cb], b1 = bias[cb + 1];
            *(float2*)(C + (size_t)rm * G4_ + cb) =
                make_float2(acc[mt][nt][0] + b0, acc[mt][nt][1] + b1);
            *(float2*)(C + (size_t)(rm + 8) * G4_ + cb) =
                make_float2(acc[mt][nt][2] + b0, acc[mt][nt][3] + b1);
        }
    }
}

// ---------------- two-level grid barrier -------------------------------------
// 128 blocks: 16 arrivals -> one of 8 group counters (128B apart), group-last
// resets its counter and arrives at root; root-last resets root, bumps gen.
__device__ __forceinline__ void grid_barrier(int gid) {
    __syncthreads();
    if (threadIdx.x == 0) {
        __threadfence();                                   // release
        unsigned g = *((volatile unsigned*)&g_gen);
        unsigned a = atomicAdd(&g_cnt8[gid * 32], 1u) + 1u;
        if (a == 16u) {
            g_cnt8[gid * 32] = 0;
            __threadfence();
            unsigned r = atomicAdd(&g_root, 1u) + 1u;
            if (r == 8u) {
                g_root = 0;
                __threadfence();
                *((volatile unsigned*)&g_gen) = g + 1u;    // release gen
            }
        }
        while (*((volatile unsigned*)&g_gen) == g) { __nanosleep(32); }
        __threadfence();                                   // acquire
    }
    __syncthreads();
}

// ---------------- tensor-core persistent recurrence --------------------------
static constexpr int WL_OFF  = 0;         // 65536 B
static constexpr int HH_OFF  = 65536;     // 65536 B (also Wh staging in prologue)
static constexpr int HL_OFF  = 131072;    // 65536 B
static constexpr int RED_OFF = 196608;    // 8 x 32cols x 34pad x 4B = 34816 B
static constexpr int LSTM_SMEM = 231424;

__global__ __launch_bounds__(256)
void lstm_tc_k(const __nv_bfloat16* __restrict__ WhH,
               const __nv_bfloat16* __restrict__ WhL,
               const float* __restrict__ gates,
               float* __restrict__ seq_out) {
    extern __shared__ char smem[];
    float* red = (float*)(smem + RED_OFF);
    const uint32_t sbase   = smem_u32(smem);
    const uint32_t wl_base = sbase + WL_OFF;
    const uint32_t hh_base = sbase + HH_OFF;
    const uint32_t hl_base = sbase + HL_OFF;

    const int tid  = threadIdx.x;
    const int wid  = tid >> 5;
    const int lane = tid & 31;
    const int j0   = blockIdx.x * 8;
    const int gid  = blockIdx.x & 7;

    // zero the global bf16 h buffers (exact cover: 128 blk * 256 thr = 32768)
    {
        int i = blockIdx.x * 256 + tid;
        g_hhA[i] = __nv_bfloat16(0.f); g_hlA[i] = __nv_bfloat16(0.f);
        g_hhB[i] = __nv_bfloat16(0.f); g_hlB[i] = __nv_bfloat16(0.f);
    }

    // ---- prologue: stage Whh hi (HH area) and lo (WL area) -----------------
    for (int idx = tid; idx < 32 * 128; idx += 256) {
        int r = idx >> 7, f = idx & 127;
        int grow = (r >> 3) * H_ + j0 + (r & 7);
        int dst = (f >> 3) * 4096 + r * 128 + (((f & 7) ^ (r & 7)) << 4);
        *(float4*)(smem + HH_OFF + dst) = *(const float4*)(WhH + (size_t)grow * H_ + f * 8);
        *(float4*)(smem + WL_OFF + dst) = *(const float4*)(WhL + (size_t)grow * H_ + f * 8);
    }
    __syncthreads();

    const int lrA0 = (lane & 15);
    const int lrB0 = (lane & 7);
    const int kselA = lane >> 4;
    const int kselB = (lane >> 3) & 1;

    // preload Whh-hi fragments: [mt][ks][4] = 64 regs
    uint32_t wh[2][8][4];
#pragma unroll
    for (int mt = 0; mt < 2; mt++)
#pragma unroll
        for (int ks = 0; ks < 8; ks++) {
            int c  = wid * 2 + (ks >> 2);
            int ua = (ks & 3) * 2 + kselA;
            int lr = mt * 16 + lrA0;
            ldmx4(wh[mt][ks], hh_base + (uint32_t)(c * 4096 + lr * 128 + ((ua ^ (lr & 7)) << 4)));
        }
    grid_barrier(gid);   // h zeroing visible; HH smem free for h staging

    float c_reg = 0.f;   // cell state for (unit=wid, batch=lane)

    for (int t = 0; t < T_; t++) {
        const __nv_bfloat16* hhin = (t & 1) ? g_hhB : g_hhA;
        const __nv_bfloat16* hlin = (t & 1) ? g_hlB : g_hlA;
        __nv_bfloat16* hhout = (t & 1) ? g_hhA : g_hhB;
        __nv_bfloat16* hlout = (t & 1) ? g_hlA : g_hlB;
        const float* gates_t = gates + (size_t)t * B_ * G4_;

        // stage gate pre-activations into red[7] (coalesced)
        {
            int b = tid >> 3, q = tid & 7, g = q >> 1, half = q & 1;
            float4 v = *(const float4*)(gates_t + (size_t)b * G4_ + g * H_ + j0 + half * 4);
            float* rp = red + 7 * 1088 + b * 34 + g * 8 + half * 4;
            rp[0] = v.x; rp[1] = v.y; rp[2] = v.z; rp[3] = v.w;
        }
        // stage h hi/lo -> swizzled chunk tiles (L2-scope loads)
        {
            const float4* hh4 = (const float4*)hhin;
            const float4* hl4 = (const float4*)hlin;
#pragma unroll
            for (int v2 = 0; v2 < 16; v2++) {
                int idx = v2 * 256 + tid;
                int row = idx >> 7, f = idx & 127;
                int dst = (f >> 3) * 4096 + row * 128 + (((f & 7) ^ (row & 7)) << 4);
                *(float4*)(smem + HH_OFF + dst) = __ldcg(hh4 + idx);
                *(float4*)(smem + HL_OFF + dst) = __ldcg(hl4 + idx);
            }
        }
        __syncthreads();

        // ---- MMA phase: 3 products over this warp's K slice ----------------
        float acc[2][4][4];
#pragma unroll
        for (int mt = 0; mt < 2; mt++)
#pragma unroll
            for (int nt = 0; nt < 4; nt++)
#pragma unroll
                for (int q = 0; q < 4; q++) acc[mt][nt][q] = 0.f;

#pragma unroll
        for (int ks = 0; ks < 8; ks++) {
            int c  = wid * 2 + (ks >> 2);
            int klo = (ks & 3) * 2;
            uint32_t al[2][4], bh[4][2], bl[4][2];
#pragma unroll
            for (int mt = 0; mt < 2; mt++) {
                int lr = mt * 16 + lrA0;
                int ua = klo + kselA;
                ldmx4(al[mt], wl_base + (uint32_t)(c * 4096 + lr * 128 + ((ua ^ (lr & 7)) << 4)));
            }
#pragma unroll
            for (int nt = 0; nt < 4; nt++) {
                int lr = nt * 8 + lrB0;
                int ub = klo + kselB;
                uint32_t off = (uint32_t)(c * 4096 + lr * 128 + ((ub ^ (lr & 7)) << 4));
                ldmx2(bh[nt], hh_base + off);
                ldmx2(bl[nt], hl_base + off);
            }
#pragma unroll
            for (int mt = 0; mt < 2; mt++)
#pragma unroll
                for (int nt = 0; nt < 4; nt++) {
                    mma16816(acc[mt][nt], wh[mt][ks], bh[nt]);   // wh*hh
                    mma16816(acc[mt][nt], wh[mt][ks], bl[nt]);   // wh*hl
                    mma16816(acc[mt][nt], al[mt],     bh[nt]);   // wl*hh
                }
        }

        // ---- cross-warp reduction into red [w][col][row(pad 34)] ----------
        {
            const int qr = lane >> 2;
            const int qc = (lane & 3) * 2;
#pragma unroll
            for (int mt = 0; mt < 2; mt++)
#pragma unroll
                for (int nt = 0; nt < 4; nt++) {
                    int row = mt * 16 + qr;
                    int col = nt * 8 + qc;
                    if (wid < 7) {
                        float* rp = red + wid * 1088;
                        rp[col * 34 + row]           = acc[mt][nt][0];
                        rp[(col + 1) * 34 + row]     = acc[mt][nt][1];
                        rp[col * 34 + row + 8]       = acc[mt][nt][2];
                        rp[(col + 1) * 34 + row + 8] = acc[mt][nt][3];
                    } else {
                        float* rp = red + 7 * 1088;
                        rp[col * 34 + row]           += acc[mt][nt][0];
                        rp[(col + 1) * 34 + row]     += acc[mt][nt][1];
                        rp[col * 34 + row + 8]       += acc[mt][nt][2];
                        rp[(col + 1) * 34 + row + 8] += acc[mt][nt][3];
                    }
                }
        }
        __syncthreads();

        // ---- LSTM elementwise update: thread = (unit u = wid, batch = lane)
        {
            const int u = wid, b = lane;
            float s[4];
#pragma unroll
            for (int g = 0; g < 4; g++) {
                float v = 0.f;
#pragma unroll
                for (int w2 = 0; w2 < 8; w2++)
                    v += red[w2 * 1088 + b * 34 + g * 8 + u];
                s[g] = v;
            }
            float si = 1.f / (1.f + expf(-s[0]));
            float sf = 1.f / (1.f + expf(-s[1]));
            float tg = tanhf(s[2]);
            float so = 1.f / (1.f + expf(-s[3]));
            c_reg = sf * c_reg + si * tg;
            float hn = so * tanhf(c_reg);

            int j = j0 + u;
            __nv_bfloat16 hh = __float2bfloat16(hn);
            __nv_bfloat16 hl = __float2bfloat16(hn - __bfloat162float(hh));
            hhout[b * H_ + j] = hh;
            hlout[b * H_ + j] = hl;
            if (seq_out) seq_out[(size_t)t * B_ * H_ + b * H_ + j] = hn;
            if (t == T_ - 1) g_h0[b * H_ + j] = hn;
        }

        grid_barrier(gid);   // h(t) globally visible before step t+1 stages it
    }
}

// ---------------- head: logits + log_softmax + NLL loss ----------------------
__global__ void head_k(const float* __restrict__ fcW, const float* __restrict__ fcb,
                       const int* __restrict__ labels, float* __restrict__ out,
                       int out_size) {
    __shared__ float lg[B_ * NL_];
    __shared__ float lsum[B_];
    int tid = threadIdx.x;

    if (tid < B_ * NL_) {
        int b = tid / NL_, n = tid % NL_;
        const float4* h4 = (const float4*)(g_h0 + b * H_);
        const float4* w4 = (const float4*)(fcW + n * H_);
        float s = 0.f;
        for (int k = 0; k < H_ / 4; k++) {
            float4 a = h4[k], w = w4[k];
            s += a.x * w.x + a.y * w.y + a.z * w.z + a.w * w.w;
        }
        lg[tid] = s + fcb[n];
    }
    __syncthreads();

    if (tid < B_) {
        float m = -1e30f;
        for (int n = 0; n < NL_; n++) m = fmaxf(m, lg[tid * NL_ + n]);
        float se = 0.f;
        for (int n = 0; n < NL_; n++) se += expf(lg[tid * NL_ + n] - m);
        float lse = m + logf(se);
        int lab = labels[tid];
        lsum[tid] = -(lg[tid * NL_ + lab] - lse);
    }
    __syncthreads();

    if (tid == 0) {
        float L = 0.f;
        for (int b = 0; b < B_; b++) L += lsum[b];
        L /= (float)B_;
        if (out_size >= 1 + B_ * NL_) {
            out[0] = L;
            for (int i = 0; i < B_ * NL_; i++) out[1 + i] = lg[i];
            for (int i = 1 + B_ * NL_; i < out_size; i++) out[i] = 0.f;
        } else if (out_size == B_ * NL_) {
            for (int i = 0; i < B_ * NL_; i++) out[i] = lg[i];
        } else if (out_size >= 1) {
            out[0] = L;
            for (int i = 1; i < out_size; i++) out[i] = 0.f;
        }
    }
}

// ---------------- launch -----------------------------------------------------
extern "C" void kernel_launch(void* const* d_in, const int* in_sizes, int n_in,
                              void* d_out, int out_size) {
    const int*   x      = (const int*)  d_in[0];
    const int*   labels = (const int*)  d_in[1];
    const float* emb    = (const float*)d_in[2];
    const float* Wih    = (const float*)d_in[3];   // [2, 4096, 1024]
    const float* Whh    = (const float*)d_in[4];   // [2, 4096, 1024]
    const float* bias   = (const float*)d_in[5];   // [2, 4096]
    const float* fcW    = (const float*)d_in[6];   // [5, 1024]
    const float* fcb    = (const float*)d_in[7];   // [5]

    cudaFuncSetAttribute(lstm_tc_k, cudaFuncAttributeMaxDynamicSharedMemorySize,
                         LSTM_SMEM);
    cudaFuncSetAttribute(gemm_mma_k, cudaFuncAttributeMaxDynamicSharedMemorySize,
                         GEMM_SMEM);

    float *seq0, *seq1, *gates;
    __nv_bfloat16 *Ah, *Al, *Wh, *Wl, *WhH, *WhL;
    cudaGetSymbolAddress((void**)&seq0,  g_seq0);
    cudaGetSymbolAddress((void**)&seq1,  g_seq1);
    cudaGetSymbolAddress((void**)&gates, g_gates);
    cudaGetSymbolAddress((void**)&Ah, g_Ah);
    cudaGetSymbolAddress((void**)&Al, g_Al);
    cudaGetSymbolAddress((void**)&Wh, g_Wh);
    cudaGetSymbolAddress((void**)&Wl, g_Wl);
    cudaGetSymbolAddress((void**)&WhH, g_WhH);
    cudaGetSymbolAddress((void**)&WhL, g_WhL);

    // 0. split weights to bf16 hi/lo (input + recurrent)
    {
        int n4 = 2 * G4_ * H_ / 4;
        split_bf16_k<<<(n4 + 255) / 256, 256>>>(Wih, Wh, Wl, n4);
        split_bf16_k<<<(n4 + 255) / 256, 256>>>(Whh, WhH, WhL, n4);
    }
    // 1. embed -> g_seq0 (time-major [T, B, H])
    embed_k<<<T_ * B_, 256>>>(x, emb);

    for (int l = 0; l < 2; l++) {
        const float* A = (l == 0) ? seq0 : seq1;
        // 2a. split A to bf16 hi/lo
        int n4 = T_ * B_ * H_ / 4;
        split_bf16_k<<<(n4 + 255) / 256, 256>>>(A, Ah, Al, n4);
        // 2b. tensor-core input GEMM (double-buffered)
        gemm_mma_k<<<dim3(G4_ / 128, (T_ * B_) / 128), 256, GEMM_SMEM>>>(
            Ah, Al, Wh + (size_t)l * G4_ * H_, Wl + (size_t)l * G4_ * H_,
            bias + (size_t)l * G4_, gates);
        // 3. tensor-core persistent recurrence
        float* seq_out = (l == 0) ? seq1 : nullptr;
        lstm_tc_k<<<NBLK, 256, LSTM_SMEM>>>(
            WhH + (size_t)l * G4_ * H_, WhL + (size_t)l * G4_ * H_,
            gates, seq_out);
    }

    // 4. head
    head_k<<<1, 256>>>(fcW, fcb, labels, (float*)d_out, out_size);
}

// round 13
// speedup vs baseline: 1.2460x; 1.2460x over previous
#include <cuda_runtime.h>
#include <cuda_bf16.h>
#include <math.h>
#include <stdint.h>

// Problem constants
static constexpr int T_   = 512;
static constexpr int B_   = 32;
static constexpr int H_   = 1024;
static constexpr int G4_  = 4096;   // 4*H
static constexpr int NL_  = 5;
static constexpr int NBLK = 128;    // persistent grid size

// ---------------- scratch (device globals; no allocations allowed) ----------
__device__ float g_gates[(size_t)T_ * B_ * G4_];
__device__ float g_h0[B_ * H_];                   // final h (for head)
__device__ unsigned int g_bar_count = 0;
__device__ unsigned int g_bar_gen   = 0;
// split-bf16 activations (layer input, time-major [T,B,H]); layer-0 LSTM
// overwrites these in place with its h outputs (input for layer-1 GEMM).
__device__ __nv_bfloat16 g_Ah[(size_t)T_ * B_ * H_];
__device__ __nv_bfloat16 g_Al[(size_t)T_ * B_ * H_];
// split-bf16 input-GEMM weights
__device__ __nv_bfloat16 g_Wh[(size_t)2 * G4_ * H_];
__device__ __nv_bfloat16 g_Wl[(size_t)2 * G4_ * H_];
// split-bf16 recurrent weights
__device__ __nv_bfloat16 g_WhH[(size_t)2 * G4_ * H_];
__device__ __nv_bfloat16 g_WhL[(size_t)2 * G4_ * H_];
// double-buffered bf16 hidden state (hi/lo), [B][H] row-major
__device__ __nv_bfloat16 g_hhA[B_ * H_];
__device__ __nv_bfloat16 g_hlA[B_ * H_];
__device__ __nv_bfloat16 g_hhB[B_ * H_];
__device__ __nv_bfloat16 g_hlB[B_ * H_];

__device__ __forceinline__ uint32_t smem_u32(const void* p) {
    uint32_t a;
    asm("{ .reg .u64 t; cvta.to.shared.u64 t, %1; cvt.u32.u64 %0, t; }" : "=r"(a) : "l"(p));
    return a;
}
__device__ __forceinline__ void mma16816(float* c, const uint32_t* a, const uint32_t* b) {
    asm volatile(
        "mma.sync.aligned.m16n8k16.row.col.f32.bf16.bf16.f32 "
        "{%0,%1,%2,%3}, {%4,%5,%6,%7}, {%8,%9}, {%0,%1,%2,%3};"
        : "+f"(c[0]), "+f"(c[1]), "+f"(c[2]), "+f"(c[3])
        : "r"(a[0]), "r"(a[1]), "r"(a[2]), "r"(a[3]), "r"(b[0]), "r"(b[1]));
}
__device__ __forceinline__ void ldmx4(uint32_t* r, uint32_t addr) {
    asm volatile("ldmatrix.sync.aligned.m8n8.x4.shared.b16 {%0,%1,%2,%3}, [%4];"
                 : "=r"(r[0]), "=r"(r[1]), "=r"(r[2]), "=r"(r[3]) : "r"(addr));
}
__device__ __forceinline__ void ldmx2(uint32_t* r, uint32_t addr) {
    asm volatile("ldmatrix.sync.aligned.m8n8.x2.shared.b16 {%0,%1}, [%2];"
                 : "=r"(r[0]), "=r"(r[1]) : "r"(addr));
}
__device__ __forceinline__ void cp_async16(uint32_t saddr, const void* g) {
    asm volatile("cp.async.cg.shared.global [%0], [%1], 16;" :: "r"(saddr), "l"(g) : "memory");
}
__device__ __forceinline__ void cp_async_wait_all() {
    asm volatile("cp.async.commit_group;\n\tcp.async.wait_group 0;" ::: "memory");
}

// ---------------- embedding gather + bf16 hi/lo split (fused) ---------------
__global__ void embed_k(const int* __restrict__ x, const float* __restrict__ emb) {
    int tb = blockIdx.x;            // tb = t*B + b  (time-major)
    int t = tb / B_;
    int b = tb % B_;
    int tok = x[b * T_ + t];
    float4 v = ((const float4*)(emb + (size_t)tok * H_))[threadIdx.x];
    __nv_bfloat16 h0 = __float2bfloat16(v.x);
    __nv_bfloat16 h1 = __float2bfloat16(v.y);
    __nv_bfloat16 h2 = __float2bfloat16(v.z);
    __nv_bfloat16 h3 = __float2bfloat16(v.w);
    __nv_bfloat16 l0 = __float2bfloat16(v.x - __bfloat162float(h0));
    __nv_bfloat16 l1 = __float2bfloat16(v.y - __bfloat162float(h1));
    __nv_bfloat16 l2 = __float2bfloat16(v.z - __bfloat162float(h2));
    __nv_bfloat16 l3 = __float2bfloat16(v.w - __bfloat162float(h3));
    __nv_bfloat162* hp = (__nv_bfloat162*)(g_Ah + (size_t)tb * H_) + threadIdx.x * 2;
    __nv_bfloat162* lp = (__nv_bfloat162*)(g_Al + (size_t)tb * H_) + threadIdx.x * 2;
    hp[0] = __nv_bfloat162(h0, h1); hp[1] = __nv_bfloat162(h2, h3);
    lp[0] = __nv_bfloat162(l0, l1); lp[1] = __nv_bfloat162(l2, l3);
}

// ---------------- fp32 -> bf16 (hi, lo) split (weights only) ----------------
__global__ void split_bf16_k(const float* __restrict__ src,
                             __nv_bfloat16* __restrict__ hi,
                             __nv_bfloat16* __restrict__ lo, int n4) {
    int i = blockIdx.x * blockDim.x + threadIdx.x;
    if (i >= n4) return;
    float4 v = ((const float4*)src)[i];
    __nv_bfloat16 h0 = __float2bfloat16(v.x);
    __nv_bfloat16 h1 = __float2bfloat16(v.y);
    __nv_bfloat16 h2 = __float2bfloat16(v.z);
    __nv_bfloat16 h3 = __float2bfloat16(v.w);
    __nv_bfloat16 l0 = __float2bfloat16(v.x - __bfloat162float(h0));
    __nv_bfloat16 l1 = __float2bfloat16(v.y - __bfloat162float(h1));
    __nv_bfloat16 l2 = __float2bfloat16(v.z - __bfloat162float(h2));
    __nv_bfloat16 l3 = __float2bfloat16(v.w - __bfloat162float(h3));
    __nv_bfloat162* hp = (__nv_bfloat162*)hi;
    __nv_bfloat162* lp = (__nv_bfloat162*)lo;
    hp[2 * i]     = __nv_bfloat162(h0, h1);
    hp[2 * i + 1] = __nv_bfloat162(h2, h3);
    lp[2 * i]     = __nv_bfloat162(l0, l1);
    lp[2 * i + 1] = __nv_bfloat162(l2, l3);
}

// ---------------- mma.sync split-bf16 input GEMM (R10-exact, known 55.9%) ---
__global__ __launch_bounds__(256)
void gemm_mma_k(const __nv_bfloat16* __restrict__ Ah, const __nv_bfloat16* __restrict__ Al,
                const __nv_bfloat16* __restrict__ Wh, const __nv_bfloat16* __restrict__ Wl,
                const float* __restrict__ bias, float* __restrict__ C) {
    __shared__ __nv_bfloat16 As[128 * 64];
    __shared__ __nv_bfloat16 Ws[128 * 64];

    const int tid  = threadIdx.x;
    const int warp = tid >> 5;
    const int lane = tid & 31;
    const int wm = warp >> 2;
    const int wn = warp & 3;
    const int m0 = blockIdx.y * 128;
    const int n0 = blockIdx.x * 128;

    const __nv_bfloat16* srcA[3] = {Ah, Ah, Al};
    const __nv_bfloat16* srcW[3] = {Wh, Wl, Wh};

    int rowL[4], uL[4], dstL[4];
#pragma unroll
    for (int i = 0; i < 4; i++) {
        int idx = i * 256 + tid;
        rowL[i] = idx >> 3;
        uL[i]   = idx & 7;
        dstL[i] = rowL[i] * 64 + ((uL[i] ^ (rowL[i] & 7)) << 3);
    }

    float acc[4][4][4];
#pragma unroll
    for (int mt = 0; mt < 4; mt++)
#pragma unroll
        for (int nt = 0; nt < 4; nt++)
#pragma unroll
            for (int q = 0; q < 4; q++) acc[mt][nt][q] = 0.f;

    int lrowA[4], lrowB[4];
#pragma unroll
    for (int mt = 0; mt < 4; mt++) lrowA[mt] = wm * 64 + mt * 16 + (lane & 15);
#pragma unroll
    for (int nt = 0; nt < 4; nt++) lrowB[nt] = wn * 32 + nt * 8 + (lane & 7);
    const uint32_t a_base = smem_u32(As);
    const uint32_t w_base = smem_u32(Ws);

    float4 pa[4], pw[4];
#pragma unroll
    for (int i = 0; i < 4; i++) {
        pa[i] = *(const float4*)(srcA[0] + (size_t)(m0 + rowL[i]) * H_ + uL[i] * 8);
        pw[i] = *(const float4*)(srcW[0] + (size_t)(n0 + rowL[i]) * H_ + uL[i] * 8);
    }

    for (int it = 0; it < 48; it++) {
#pragma unroll
        for (int i = 0; i < 4; i++) {
            *(float4*)(As + dstL[i]) = pa[i];
            *(float4*)(Ws + dstL[i]) = pw[i];
        }
        __syncthreads();

        if (it + 1 < 48) {
            int p2 = (it + 1) >> 4;
            int kcol2 = ((it + 1) & 15) * 64;
#pragma unroll
            for (int i = 0; i < 4; i++) {
                pa[i] = *(const float4*)(srcA[p2] + (size_t)(m0 + rowL[i]) * H_ + kcol2 + uL[i] * 8);
                pw[i] = *(const float4*)(srcW[p2] + (size_t)(n0 + rowL[i]) * H_ + kcol2 + uL[i] * 8);
            }
        }

#pragma unroll
        for (int ks = 0; ks < 4; ks++) {
            uint32_t af[4][4], bf[4][2];
            int ua = ks * 2 + (lane >> 4);
#pragma unroll
            for (int mt = 0; mt < 4; mt++)
                ldmx4(af[mt], a_base + (uint32_t)(lrowA[mt] * 128 + ((ua ^ (lrowA[mt] & 7)) << 4)));
            int ub = ks * 2 + ((lane >> 3) & 1);
#pragma unroll
            for (int nt = 0; nt < 4; nt++)
                ldmx2(bf[nt], w_base + (uint32_t)(lrowB[nt] * 128 + ((ub ^ (lrowB[nt] & 7)) << 4)));
#pragma unroll
            for (int mt = 0; mt < 4; mt++)
#pragma unroll
                for (int nt = 0; nt < 4; nt++)
                    mma16816(acc[mt][nt], af[mt], bf[nt]);
        }
        __syncthreads();
    }

    const int qr = lane >> 2;
    const int qc = (lane & 3) * 2;
#pragma unroll
    for (int mt = 0; mt < 4; mt++) {
        int rm = m0 + wm * 64 + mt * 16 + qr;
#pragma unroll
        for (int nt = 0; nt < 4; nt++) {
            int cb = n0 + wn * 32 + nt * 8 + qc;
            float b0 = bias[cb], b1 = bias[cb + 1];
            *(float2*)(C + (size_t)rm * G4_ + cb) =
                make_float2(acc[mt][nt][0] + b0, acc[mt][nt][1] + b1);
            *(float2*)(C + (size_t)(rm + 8) * G4_ + cb) =
                make_float2(acc[mt][nt][2] + b0, acc[mt][nt][3] + b1);
        }
    }
}

// ---------------- flat grid barrier (R10-exact; atomics stream at L2) -------
__device__ __forceinline__ void grid_barrier() {
    __syncthreads();
    if (threadIdx.x == 0) {
        __threadfence();
        unsigned g = *((volatile unsigned*)&g_bar_gen);
        unsigned arrived = atomicAdd(&g_bar_count, 1u) + 1u;
        if (arrived == (unsigned)NBLK) {
            g_bar_count = 0;
            __threadfence();
            atomicAdd(&g_bar_gen, 1u);
        } else {
            while (*((volatile unsigned*)&g_bar_gen) == g) { __nanosleep(64); }
        }
    }
    __syncthreads();
}

// ---------------- tensor-core persistent recurrence --------------------------
// 128 blocks x 256 threads (8 warps); block owns 8 hidden units = 32 gate rows.
// Whh hi AND lo fragments live in registers (loop-invariant); per step only h
// (hi/lo) is staged into smem via cp.async.cg, swizzled for ldmatrix.
static constexpr int HH_OFF  = 0;         // 65536 B (Whh-hi staging in prologue)
static constexpr int HL_OFF  = 65536;     // 65536 B (Whh-lo staging in prologue)
static constexpr int RED_OFF = 131072;    // 8 x 32cols x 34pad x 4B = 34816 B
static constexpr int LSTM_SMEM = 165888;

__global__ __launch_bounds__(256, 1)
void lstm_tc_k(const __nv_bfloat16* __restrict__ WhH,
               const __nv_bfloat16* __restrict__ WhL,
               const float* __restrict__ gates,
               __nv_bfloat16* __restrict__ aoh,   // layer-0: write h as bf16 hi
               __nv_bfloat16* __restrict__ aol) { // layer-0: write h as bf16 lo
    extern __shared__ char smem[];
    float* red = (float*)(smem + RED_OFF);
    const uint32_t sbase   = smem_u32(smem);
    const uint32_t hh_base = sbase + HH_OFF;
    const uint32_t hl_base = sbase + HL_OFF;

    const int tid  = threadIdx.x;
    const int wid  = tid >> 5;
    const int lane = tid & 31;
    const int j0   = blockIdx.x * 8;

    // zero the global bf16 h buffers (exact cover: 128 blk * 256 thr = 32768)
    {
        int i = blockIdx.x * 256 + tid;
        g_hhA[i] = __nv_bfloat16(0.f); g_hlA[i] = __nv_bfloat16(0.f);
        g_hhB[i] = __nv_bfloat16(0.f); g_hlB[i] = __nv_bfloat16(0.f);
    }

    // ---- prologue: stage Whh hi -> HH, lo -> HL, then load fragments -------
    for (int idx = tid; idx < 32 * 128; idx += 256) {
        int r = idx >> 7, f = idx & 127;
        int grow = (r >> 3) * H_ + j0 + (r & 7);
        int dst = (f >> 3) * 4096 + r * 128 + (((f & 7) ^ (r & 7)) << 4);
        *(float4*)(smem + HH_OFF + dst) = *(const float4*)(WhH + (size_t)grow * H_ + f * 8);
        *(float4*)(smem + HL_OFF + dst) = *(const float4*)(WhL + (size_t)grow * H_ + f * 8);
    }
    __syncthreads();

    const int lrA0 = (lane & 15);
    const int lrB0 = (lane & 7);
    const int kselA = lane >> 4;
    const int kselB = (lane >> 3) & 1;

    // Whh hi AND lo fragments in registers: [mt][ks][4] x2 = 128 regs
    uint32_t wh[2][8][4], wl[2][8][4];
#pragma unroll
    for (int mt = 0; mt < 2; mt++)
#pragma unroll
        for (int ks = 0; ks < 8; ks++) {
            int c  = wid * 2 + (ks >> 2);
            int ua = (ks & 3) * 2 + kselA;
            int lr = mt * 16 + lrA0;
            uint32_t off = (uint32_t)(c * 4096 + lr * 128 + ((ua ^ (lr & 7)) << 4));
            ldmx4(wh[mt][ks], hh_base + off);
            ldmx4(wl[mt][ks], hl_base + off);
        }
    grid_barrier();   // h zeroing visible; HH/HL smem free for h staging

    float c_reg = 0.f;   // cell state for (unit=wid, batch=lane)

    for (int t = 0; t < T_; t++) {
        const __nv_bfloat16* hhin = (t & 1) ? g_hhB : g_hhA;
        const __nv_bfloat16* hlin = (t & 1) ? g_hlB : g_hlA;
        __nv_bfloat16* hhout = (t & 1) ? g_hhA : g_hhB;
        __nv_bfloat16* hlout = (t & 1) ? g_hlA : g_hlB;
        const float* gates_t = gates + (size_t)t * B_ * G4_;

        // stage h hi/lo -> swizzled chunk tiles via cp.async (L2-sourced)
#pragma unroll
        for (int v2 = 0; v2 < 16; v2++) {
            int idx = v2 * 256 + tid;
            int row = idx >> 7, f = idx & 127;
            uint32_t dst = (uint32_t)((f >> 3) * 4096 + row * 128 + (((f & 7) ^ (row & 7)) << 4));
            cp_async16(hh_base + dst, (const char*)hhin + idx * 16);
            cp_async16(hl_base + dst, (const char*)hlin + idx * 16);
        }
        // stage gate pre-activations into red[7] (overlaps with cp.async)
        {
            int b = tid >> 3, q = tid & 7, g = q >> 1, half = q & 1;
            float4 v = *(const float4*)(gates_t + (size_t)b * G4_ + g * H_ + j0 + half * 4);
            float* rp = red + 7 * 1088 + b * 34 + g * 8 + half * 4;
            rp[0] = v.x; rp[1] = v.y; rp[2] = v.z; rp[3] = v.w;
        }
        cp_async_wait_all();
        __syncthreads();

        // ---- MMA phase: weights from registers, h from smem ----------------
        float acc[2][4][4];
#pragma unroll
        for (int mt = 0; mt < 2; mt++)
#pragma unroll
            for (int nt = 0; nt < 4; nt++)
#pragma unroll
                for (int q = 0; q < 4; q++) acc[mt][nt][q] = 0.f;

#pragma unroll
        for (int ks = 0; ks < 8; ks++) {
            int c  = wid * 2 + (ks >> 2);
            int klo = (ks & 3) * 2;
            uint32_t bh[4][2], bl[4][2];
#pragma unroll
            for (int nt = 0; nt < 4; nt++) {
                int lr = nt * 8 + lrB0;
                int ub = klo + kselB;
                uint32_t off = (uint32_t)(c * 4096 + lr * 128 + ((ub ^ (lr & 7)) << 4));
                ldmx2(bh[nt], hh_base + off);
                ldmx2(bl[nt], hl_base + off);
            }
#pragma unroll
            for (int mt = 0; mt < 2; mt++)
#pragma unroll
                for (int nt = 0; nt < 4; nt++) {
                    mma16816(acc[mt][nt], wh[mt][ks], bh[nt]);   // wh*hh
                    mma16816(acc[mt][nt], wh[mt][ks], bl[nt]);   // wh*hl
                    mma16816(acc[mt][nt], wl[mt][ks], bh[nt]);   // wl*hh
                }
        }

        // ---- cross-warp reduction into red [w][col][row(pad 34)] ----------
        {
            const int qr = lane >> 2;
            const int qc = (lane & 3) * 2;
#pragma unroll
            for (int mt = 0; mt < 2; mt++)
#pragma unroll
                for (int nt = 0; nt < 4; nt++) {
                    int row = mt * 16 + qr;
                    int col = nt * 8 + qc;
                    if (wid < 7) {
                        float* rp = red + wid * 1088;
                        rp[col * 34 + row]           = acc[mt][nt][0];
                        rp[(col + 1) * 34 + row]     = acc[mt][nt][1];
                        rp[col * 34 + row + 8]       = acc[mt][nt][2];
                        rp[(col + 1) * 34 + row + 8] = acc[mt][nt][3];
                    } else {
                        float* rp = red + 7 * 1088;
                        rp[col * 34 + row]           += acc[mt][nt][0];
                        rp[(col + 1) * 34 + row]     += acc[mt][nt][1];
                        rp[col * 34 + row + 8]       += acc[mt][nt][2];
                        rp[(col + 1) * 34 + row + 8] += acc[mt][nt][3];
                    }
                }
        }
        __syncthreads();

        // ---- LSTM elementwise update: thread = (unit u = wid, batch = lane)
        {
            const int u = wid, b = lane;
            float s[4];
#pragma unroll
            for (int g = 0; g < 4; g++) {
                float v = 0.f;
#pragma unroll
                for (int w2 = 0; w2 < 8; w2++)
                    v += red[w2 * 1088 + b * 34 + g * 8 + u];
                s[g] = v;
            }
            float si = 1.f / (1.f + expf(-s[0]));
            float sf = 1.f / (1.f + expf(-s[1]));
            float tg = tanhf(s[2]);
            float so = 1.f / (1.f + expf(-s[3]));
            c_reg = sf * c_reg + si * tg;
            float hn = so * tanhf(c_reg);

            int j = j0 + u;
            __nv_bfloat16 hh = __float2bfloat16(hn);
            __nv_bfloat16 hl = __float2bfloat16(hn - __bfloat162float(hh));
            hhout[b * H_ + j] = hh;
            hlout[b * H_ + j] = hl;
            if (aoh) {   // layer 0: feed layer-1 GEMM directly (bf16 hi/lo)
                size_t o = (size_t)t * B_ * H_ + b * H_ + j;
                aoh[o] = hh;
                aol[o] = hl;
            }
            if (t == T_ - 1) g_h0[b * H_ + j] = hn;
        }

        grid_barrier();   // h(t) globally visible before step t+1 stages it
    }
}

// ---------------- head: logits + log_softmax + NLL loss ----------------------
__global__ void head_k(const float* __restrict__ fcW, const float* __restrict__ fcb,
                       const int* __restrict__ labels, float* __restrict__ out,
                       int out_size) {
    __shared__ float lg[B_ * NL_];
    __shared__ float lsum[B_];
    int tid = threadIdx.x;

    if (tid < B_ * NL_) {
        int b = tid / NL_, n = tid % NL_;
        const float4* h4 = (const float4*)(g_h0 + b * H_);
        const float4* w4 = (const float4*)(fcW + n * H_);
        float s = 0.f;
        for (int k = 0; k < H_ / 4; k++) {
            float4 a = h4[k], w = w4[k];
            s += a.x * w.x + a.y * w.y + a.z * w.z + a.w * w.w;
        }
        lg[tid] = s + fcb[n];
    }
    __syncthreads();

    if (tid < B_) {
        float m = -1e30f;
        for (int n = 0; n < NL_; n++) m = fmaxf(m, lg[tid * NL_ + n]);
        float se = 0.f;
        for (int n = 0; n < NL_; n++) se += expf(lg[tid * NL_ + n] - m);
        float lse = m + logf(se);
        int lab = labels[tid];
        lsum[tid] = -(lg[tid * NL_ + lab] - lse);
    }
    __syncthreads();

    if (tid == 0) {
        float L = 0.f;
        for (int b = 0; b < B_; b++) L += lsum[b];
        L /= (float)B_;
        if (out_size >= 1 + B_ * NL_) {
            out[0] = L;
            for (int i = 0; i < B_ * NL_; i++) out[1 + i] = lg[i];
            for (int i = 1 + B_ * NL_; i < out_size; i++) out[i] = 0.f;
        } else if (out_size == B_ * NL_) {
            for (int i = 0; i < B_ * NL_; i++) out[i] = lg[i];
        } else if (out_size >= 1) {
            out[0] = L;
            for (int i = 1; i < out_size; i++) out[i] = 0.f;
        }
    }
}

// ---------------- launch -----------------------------------------------------
extern "C" void kernel_launch(void* const* d_in, const int* in_sizes, int n_in,
                              void* d_out, int out_size) {
    const int*   x      = (const int*)  d_in[0];
    const int*   labels = (const int*)  d_in[1];
    const float* emb    = (const float*)d_in[2];
    const float* Wih    = (const float*)d_in[3];   // [2, 4096, 1024]
    const float* Whh    = (const float*)d_in[4];   // [2, 4096, 1024]
    const float* bias   = (const float*)d_in[5];   // [2, 4096]
    const float* fcW    = (const float*)d_in[6];   // [5, 1024]
    const float* fcb    = (const float*)d_in[7];   // [5]

    cudaFuncSetAttribute(lstm_tc_k, cudaFuncAttributeMaxDynamicSharedMemorySize,
                         LSTM_SMEM);

    float *gates;
    __nv_bfloat16 *Ah, *Al, *Wh, *Wl, *WhH, *WhL;
    cudaGetSymbolAddress((void**)&gates, g_gates);
    cudaGetSymbolAddress((void**)&Ah, g_Ah);
    cudaGetSymbolAddress((void**)&Al, g_Al);
    cudaGetSymbolAddress((void**)&Wh, g_Wh);
    cudaGetSymbolAddress((void**)&Wl, g_Wl);
    cudaGetSymbolAddress((void**)&WhH, g_WhH);
    cudaGetSymbolAddress((void**)&WhL, g_WhL);

    // 0. split weights to bf16 hi/lo (input + recurrent)
    {
        int n4 = 2 * G4_ * H_ / 4;
        split_bf16_k<<<(n4 + 255) / 256, 256>>>(Wih, Wh, Wl, n4);
        split_bf16_k<<<(n4 + 255) / 256, 256>>>(Whh, WhH, WhL, n4);
    }
    // 1. embed -> g_Ah/g_Al directly (time-major [T, B, H], bf16 hi/lo)
    embed_k<<<T_ * B_, 256>>>(x, emb);

    for (int l = 0; l < 2; l++) {
        // 2. tensor-core input GEMM (A = g_Ah/g_Al; layer-0 LSTM refilled them)
        gemm_mma_k<<<dim3(G4_ / 128, (T_ * B_) / 128), 256>>>(
            Ah, Al, Wh + (size_t)l * G4_ * H_, Wl + (size_t)l * G4_ * H_,
            bias + (size_t)l * G4_, gates);
        // 3. tensor-core persistent recurrence; layer 0 writes h back into Ah/Al
        lstm_tc_k<<<NBLK, 256, LSTM_SMEM>>>(
            WhH + (size_t)l * G4_ * H_, WhL + (size_t)l * G4_ * H_,
            gates,
            (l == 0) ? Ah : ((__nv_bfloat16*)nullptr),
            (l == 0) ? Al : ((__nv_bfloat16*)nullptr));
    }

    // 4. head
    head_k<<<1, 256>>>(fcW, fcb, labels, (float*)d_out, out_size);
}

// round 15
// speedup vs baseline: 1.3139x; 1.0545x over previous
#include <cuda_runtime.h>
#include <cuda_bf16.h>
#include <math.h>
#include <stdint.h>

// Problem constants
static constexpr int T_   = 512;
static constexpr int B_   = 32;
static constexpr int H_   = 1024;
static constexpr int G4_  = 4096;   // 4*H
static constexpr int NL_  = 5;
static constexpr int NBLK = 128;    // persistent grid size

// ---------------- scratch (device globals; no allocations allowed) ----------
__device__ float g_gates[(size_t)T_ * B_ * G4_];
__device__ float g_h0[B_ * H_];                   // final h (for head)
__device__ unsigned int g_bar_count = 0;
__device__ unsigned int g_bar_gen   = 0;
// split-bf16 activations (layer input, time-major [T,B,H]); layer-0 LSTM
// overwrites these in place with its h outputs (input for layer-1 GEMM).
__device__ __nv_bfloat16 g_Ah[(size_t)T_ * B_ * H_];
__device__ __nv_bfloat16 g_Al[(size_t)T_ * B_ * H_];
// split-bf16 input-GEMM weights
__device__ __nv_bfloat16 g_Wh[(size_t)2 * G4_ * H_];
__device__ __nv_bfloat16 g_Wl[(size_t)2 * G4_ * H_];
// split-bf16 recurrent weights
__device__ __nv_bfloat16 g_WhH[(size_t)2 * G4_ * H_];
__device__ __nv_bfloat16 g_WhL[(size_t)2 * G4_ * H_];
// double-buffered bf16 hidden state (hi/lo), [B][H] row-major
__device__ __nv_bfloat16 g_hhA[B_ * H_];
__device__ __nv_bfloat16 g_hlA[B_ * H_];
__device__ __nv_bfloat16 g_hhB[B_ * H_];
__device__ __nv_bfloat16 g_hlB[B_ * H_];

__device__ __forceinline__ uint32_t smem_u32(const void* p) {
    uint32_t a;
    asm("{ .reg .u64 t; cvta.to.shared.u64 t, %1; cvt.u32.u64 %0, t; }" : "=r"(a) : "l"(p));
    return a;
}
__device__ __forceinline__ void mma16816(float* c, const uint32_t* a, const uint32_t* b) {
    asm volatile(
        "mma.sync.aligned.m16n8k16.row.col.f32.bf16.bf16.f32 "
        "{%0,%1,%2,%3}, {%4,%5,%6,%7}, {%8,%9}, {%0,%1,%2,%3};"
        : "+f"(c[0]), "+f"(c[1]), "+f"(c[2]), "+f"(c[3])
        : "r"(a[0]), "r"(a[1]), "r"(a[2]), "r"(a[3]), "r"(b[0]), "r"(b[1]));
}
__device__ __forceinline__ void ldmx4(uint32_t* r, uint32_t addr) {
    asm volatile("ldmatrix.sync.aligned.m8n8.x4.shared.b16 {%0,%1,%2,%3}, [%4];"
                 : "=r"(r[0]), "=r"(r[1]), "=r"(r[2]), "=r"(r[3]) : "r"(addr));
}
__device__ __forceinline__ void ldmx2(uint32_t* r, uint32_t addr) {
    asm volatile("ldmatrix.sync.aligned.m8n8.x2.shared.b16 {%0,%1}, [%2];"
                 : "=r"(r[0]), "=r"(r[1]) : "r"(addr));
}
__device__ __forceinline__ void cp_async16(uint32_t saddr, const void* g) {
    asm volatile("cp.async.cg.shared.global [%0], [%1], 16;" :: "r"(saddr), "l"(g) : "memory");
}

// ---------------- embedding gather + bf16 hi/lo split (fused) ---------------
__global__ void embed_k(const int* __restrict__ x, const float* __restrict__ emb) {
    int tb = blockIdx.x;            // tb = t*B + b  (time-major)
    int t = tb / B_;
    int b = tb % B_;
    int tok = x[b * T_ + t];
    float4 v = ((const float4*)(emb + (size_t)tok * H_))[threadIdx.x];
    __nv_bfloat16 h0 = __float2bfloat16(v.x);
    __nv_bfloat16 h1 = __float2bfloat16(v.y);
    __nv_bfloat16 h2 = __float2bfloat16(v.z);
    __nv_bfloat16 h3 = __float2bfloat16(v.w);
    __nv_bfloat16 l0 = __float2bfloat16(v.x - __bfloat162float(h0));
    __nv_bfloat16 l1 = __float2bfloat16(v.y - __bfloat162float(h1));
    __nv_bfloat16 l2 = __float2bfloat16(v.z - __bfloat162float(h2));
    __nv_bfloat16 l3 = __float2bfloat16(v.w - __bfloat162float(h3));
    __nv_bfloat162* hp = (__nv_bfloat162*)(g_Ah + (size_t)tb * H_) + threadIdx.x * 2;
    __nv_bfloat162* lp = (__nv_bfloat162*)(g_Al + (size_t)tb * H_) + threadIdx.x * 2;
    hp[0] = __nv_bfloat162(h0, h1); hp[1] = __nv_bfloat162(h2, h3);
    lp[0] = __nv_bfloat162(l0, l1); lp[1] = __nv_bfloat162(l2, l3);
}

// ---------------- fp32 -> bf16 (hi, lo) split (weights only) ----------------
__global__ void split_bf16_k(const float* __restrict__ src,
                             __nv_bfloat16* __restrict__ hi,
                             __nv_bfloat16* __restrict__ lo, int n4) {
    int i = blockIdx.x * blockDim.x + threadIdx.x;
    if (i >= n4) return;
    float4 v = ((const float4*)src)[i];
    __nv_bfloat16 h0 = __float2bfloat16(v.x);
    __nv_bfloat16 h1 = __float2bfloat16(v.y);
    __nv_bfloat16 h2 = __float2bfloat16(v.z);
    __nv_bfloat16 h3 = __float2bfloat16(v.w);
    __nv_bfloat16 l0 = __float2bfloat16(v.x - __bfloat162float(h0));
    __nv_bfloat16 l1 = __float2bfloat16(v.y - __bfloat162float(h1));
    __nv_bfloat16 l2 = __float2bfloat16(v.z - __bfloat162float(h2));
    __nv_bfloat16 l3 = __float2bfloat16(v.w - __bfloat162float(h3));
    __nv_bfloat162* hp = (__nv_bfloat162*)hi;
    __nv_bfloat162* lp = (__nv_bfloat162*)lo;
    hp[2 * i]     = __nv_bfloat162(h0, h1);
    hp[2 * i + 1] = __nv_bfloat162(h2, h3);
    lp[2 * i]     = __nv_bfloat162(l0, l1);
    lp[2 * i + 1] = __nv_bfloat162(l2, l3);
}

// ---------------- mma.sync split-bf16 input GEMM (R10/R13-exact) ------------
__global__ __launch_bounds__(256)
void gemm_mma_k(const __nv_bfloat16* __restrict__ Ah, const __nv_bfloat16* __restrict__ Al,
                const __nv_bfloat16* __restrict__ Wh, const __nv_bfloat16* __restrict__ Wl,
                const float* __restrict__ bias, float* __restrict__ C) {
    __shared__ __nv_bfloat16 As[128 * 64];
    __shared__ __nv_bfloat16 Ws[128 * 64];

    const int tid  = threadIdx.x;
    const int warp = tid >> 5;
    const int lane = tid & 31;
    const int wm = warp >> 2;
    const int wn = warp & 3;
    const int m0 = blockIdx.y * 128;
    const int n0 = blockIdx.x * 128;

    const __nv_bfloat16* srcA[3] = {Ah, Ah, Al};
    const __nv_bfloat16* srcW[3] = {Wh, Wl, Wh};

    int rowL[4], uL[4], dstL[4];
#pragma unroll
    for (int i = 0; i < 4; i++) {
        int idx = i * 256 + tid;
        rowL[i] = idx >> 3;
        uL[i]   = idx & 7;
        dstL[i] = rowL[i] * 64 + ((uL[i] ^ (rowL[i] & 7)) << 3);
    }

    float acc[4][4][4];
#pragma unroll
    for (int mt = 0; mt < 4; mt++)
#pragma unroll
        for (int nt = 0; nt < 4; nt++)
#pragma unroll
            for (int q = 0; q < 4; q++) acc[mt][nt][q] = 0.f;

    int lrowA[4], lrowB[4];
#pragma unroll
    for (int mt = 0; mt < 4; mt++) lrowA[mt] = wm * 64 + mt * 16 + (lane & 15);
#pragma unroll
    for (int nt = 0; nt < 4; nt++) lrowB[nt] = wn * 32 + nt * 8 + (lane & 7);
    const uint32_t a_base = smem_u32(As);
    const uint32_t w_base = smem_u32(Ws);

    float4 pa[4], pw[4];
#pragma unroll
    for (int i = 0; i < 4; i++) {
        pa[i] = *(const float4*)(srcA[0] + (size_t)(m0 + rowL[i]) * H_ + uL[i] * 8);
        pw[i] = *(const float4*)(srcW[0] + (size_t)(n0 + rowL[i]) * H_ + uL[i] * 8);
    }

    for (int it = 0; it < 48; it++) {
#pragma unroll
        for (int i = 0; i < 4; i++) {
            *(float4*)(As + dstL[i]) = pa[i];
            *(float4*)(Ws + dstL[i]) = pw[i];
        }
        __syncthreads();

        if (it + 1 < 48) {
            int p2 = (it + 1) >> 4;
            int kcol2 = ((it + 1) & 15) * 64;
#pragma unroll
            for (int i = 0; i < 4; i++) {
                pa[i] = *(const float4*)(srcA[p2] + (size_t)(m0 + rowL[i]) * H_ + kcol2 + uL[i] * 8);
                pw[i] = *(const float4*)(srcW[p2] + (size_t)(n0 + rowL[i]) * H_ + kcol2 + uL[i] * 8);
            }
        }

#pragma unroll
        for (int ks = 0; ks < 4; ks++) {
            uint32_t af[4][4], bf[4][2];
            int ua = ks * 2 + (lane >> 4);
#pragma unroll
            for (int mt = 0; mt < 4; mt++)
                ldmx4(af[mt], a_base + (uint32_t)(lrowA[mt] * 128 + ((ua ^ (lrowA[mt] & 7)) << 4)));
            int ub = ks * 2 + ((lane >> 3) & 1);
#pragma unroll
            for (int nt = 0; nt < 4; nt++)
                ldmx2(bf[nt], w_base + (uint32_t)(lrowB[nt] * 128 + ((ub ^ (lrowB[nt] & 7)) << 4)));
#pragma unroll
            for (int mt = 0; mt < 4; mt++)
#pragma unroll
                for (int nt = 0; nt < 4; nt++)
                    mma16816(acc[mt][nt], af[mt], bf[nt]);
        }
        __syncthreads();
    }

    const int qr = lane >> 2;
    const int qc = (lane & 3) * 2;
#pragma unroll
    for (int mt = 0; mt < 4; mt++) {
        int rm = m0 + wm * 64 + mt * 16 + qr;
#pragma unroll
        for (int nt = 0; nt < 4; nt++) {
            int cb = n0 + wn * 32 + nt * 8 + qc;
            float b0 = bias[cb], b1 = bias[cb + 1];
            *(float2*)(C + (size_t)rm * G4_ + cb) =
                make_float2(acc[mt][nt][0] + b0, acc[mt][nt][1] + b1);
            *(float2*)(C + (size_t)(rm + 8) * G4_ + cb) =
                make_float2(acc[mt][nt][2] + b0, acc[mt][nt][3] + b1);
        }
    }
}

// ---------------- flat grid barrier (R10-exact; atomics stream at L2) -------
__device__ __forceinline__ void grid_barrier() {
    __syncthreads();
    if (threadIdx.x == 0) {
        __threadfence();
        unsigned g = *((volatile unsigned*)&g_bar_gen);
        unsigned arrived = atomicAdd(&g_bar_count, 1u) + 1u;
        if (arrived == (unsigned)NBLK) {
            g_bar_count = 0;
            __threadfence();
            atomicAdd(&g_bar_gen, 1u);
        } else {
            while (*((volatile unsigned*)&g_bar_gen) == g) { __nanosleep(64); }
        }
    }
    __syncthreads();
}

// ---------------- tensor-core persistent recurrence --------------------------
// 128 blocks x 256 threads (8 warps); block owns 8 hidden units = 32 gate rows.
// Whh hi AND lo fragments live in registers (loop-invariant). Per step each
// WARP stages only ITS OWN h K-slice (chunks 2*wid, 2*wid+1; hi+lo = 16 KB)
// via cp.async and waits only its own group -> no block-wide sync before MMA.
// Gate pre-activations stage into reduction slot red[8]; all warps write their
// own slot red[wid]; the update sums all 9 slots after ONE __syncthreads.
static constexpr int HH_OFF  = 0;         // 65536 B
static constexpr int HL_OFF  = 65536;     // 65536 B
static constexpr int RED_OFF = 131072;    // 9 x 32cols x 34pad x 4B = 39168 B
static constexpr int LSTM_SMEM = 170240;

__global__ __launch_bounds__(256, 1)
void lstm_tc_k(const __nv_bfloat16* __restrict__ WhH,
               const __nv_bfloat16* __restrict__ WhL,
               const float* __restrict__ gates,
               __nv_bfloat16* __restrict__ aoh,   // layer-0: write h as bf16 hi
               __nv_bfloat16* __restrict__ aol) { // layer-0: write h as bf16 lo
    extern __shared__ char smem[];
    float* red = (float*)(smem + RED_OFF);
    const uint32_t sbase   = smem_u32(smem);
    const uint32_t hh_base = sbase + HH_OFF;
    const uint32_t hl_base = sbase + HL_OFF;

    const int tid  = threadIdx.x;
    const int wid  = tid >> 5;
    const int lane = tid & 31;
    const int j0   = blockIdx.x * 8;

    // zero the global bf16 h buffers (exact cover: 128 blk * 256 thr = 32768)
    {
        int i = blockIdx.x * 256 + tid;
        g_hhA[i] = __nv_bfloat16(0.f); g_hlA[i] = __nv_bfloat16(0.f);
        g_hhB[i] = __nv_bfloat16(0.f); g_hlB[i] = __nv_bfloat16(0.f);
    }

    // ---- prologue: stage Whh hi -> HH, lo -> HL, then load fragments -------
    for (int idx = tid; idx < 32 * 128; idx += 256) {
        int r = idx >> 7, f = idx & 127;
        int grow = (r >> 3) * H_ + j0 + (r & 7);
        int dst = (f >> 3) * 4096 + r * 128 + (((f & 7) ^ (r & 7)) << 4);
        *(float4*)(smem + HH_OFF + dst) = *(const float4*)(WhH + (size_t)grow * H_ + f * 8);
        *(float4*)(smem + HL_OFF + dst) = *(const float4*)(WhL + (size_t)grow * H_ + f * 8);
    }
    __syncthreads();

    const int lrA0 = (lane & 15);
    const int lrB0 = (lane & 7);
    const int kselA = lane >> 4;
    const int kselB = (lane >> 3) & 1;

    // Whh hi AND lo fragments in registers: [mt][ks][4] x2 = 128 regs
    uint32_t wh[2][8][4], wl[2][8][4];
#pragma unroll
    for (int mt = 0; mt < 2; mt++)
#pragma unroll
        for (int ks = 0; ks < 8; ks++) {
            int c  = wid * 2 + (ks >> 2);
            int ua = (ks & 3) * 2 + kselA;
            int lr = mt * 16 + lrA0;
            uint32_t off = (uint32_t)(c * 4096 + lr * 128 + ((ua ^ (lr & 7)) << 4));
            ldmx4(wh[mt][ks], hh_base + off);
            ldmx4(wl[mt][ks], hl_base + off);
        }
    grid_barrier();   // h zeroing visible; HH/HL smem free for h staging

    float c_reg = 0.f;   // cell state for (unit=wid, batch=lane)

    for (int t = 0; t < T_; t++) {
        const __nv_bfloat16* hhin = (t & 1) ? g_hhB : g_hhA;
        const __nv_bfloat16* hlin = (t & 1) ? g_hlB : g_hlA;
        __nv_bfloat16* hhout = (t & 1) ? g_hhA : g_hhB;
        __nv_bfloat16* hlout = (t & 1) ? g_hlA : g_hlB;
        const float* gates_t = gates + (size_t)t * B_ * G4_;

        // ---- warp-local h staging: this warp's chunks 2*wid, 2*wid+1 -------
        {
            const char* hh8 = (const char*)hhin;
            const char* hl8 = (const char*)hlin;
#pragma unroll
            for (int k = 0; k < 8; k++) {
                int idx = k * 32 + lane;        // 0..255 within a chunk
                int r  = idx >> 3;              // batch row 0..31
                int fc = idx & 7;               // float4 within (row, chunk)
                uint32_t sw = (uint32_t)(r * 128 + ((fc ^ (r & 7)) << 4));
#pragma unroll
                for (int cc = 0; cc < 2; cc++) {
                    int c = wid * 2 + cc;
                    uint32_t doff = (uint32_t)(c * 4096) + sw;
                    size_t goff = (size_t)((r * 128 + c * 8 + fc) * 16);
                    cp_async16(hh_base + doff, hh8 + goff);
                    cp_async16(hl_base + doff, hl8 + goff);
                }
            }
        }
        // stage gate pre-activations into red[8] (independent of cp.async)
        {
            int b = tid >> 3, q = tid & 7, g = q >> 1, half = q & 1;
            float4 v = *(const float4*)(gates_t + (size_t)b * G4_ + g * H_ + j0 + half * 4);
            float* rp = red + 8 * 1088 + b * 34 + g * 8 + half * 4;
            rp[0] = v.x; rp[1] = v.y; rp[2] = v.z; rp[3] = v.w;
        }
        asm volatile("cp.async.commit_group;\n\tcp.async.wait_group 0;" ::: "memory");
        __syncwarp();

        // ---- MMA phase: weights from registers, own-warp h from smem -------
        float acc[2][4][4];
#pragma unroll
        for (int mt = 0; mt < 2; mt++)
#pragma unroll
            for (int nt = 0; nt < 4; nt++)
#pragma unroll
                for (int q = 0; q < 4; q++) acc[mt][nt][q] = 0.f;

#pragma unroll
        for (int ks = 0; ks < 8; ks++) {
            int c  = wid * 2 + (ks >> 2);
            int klo = (ks & 3) * 2;
            uint32_t bh[4][2], bl[4][2];
#pragma unroll
            for (int nt = 0; nt < 4; nt++) {
                int lr = nt * 8 + lrB0;
                int ub = klo + kselB;
                uint32_t off = (uint32_t)(c * 4096 + lr * 128 + ((ub ^ (lr & 7)) << 4));
                ldmx2(bh[nt], hh_base + off);
                ldmx2(bl[nt], hl_base + off);
            }
#pragma unroll
            for (int mt = 0; mt < 2; mt++)
#pragma unroll
                for (int nt = 0; nt < 4; nt++) {
                    mma16816(acc[mt][nt], wh[mt][ks], bh[nt]);   // wh*hh
                    mma16816(acc[mt][nt], wh[mt][ks], bl[nt]);   // wh*hl
                    mma16816(acc[mt][nt], wl[mt][ks], bh[nt]);   // wl*hh
                }
        }

        // ---- write own partial slot red[wid] (no special cases) ------------
        {
            const int qr = lane >> 2;
            const int qc = (lane & 3) * 2;
            float* rp = red + wid * 1088;
#pragma unroll
            for (int mt = 0; mt < 2; mt++)
#pragma unroll
                for (int nt = 0; nt < 4; nt++) {
                    int row = mt * 16 + qr;
                    int col = nt * 8 + qc;
                    rp[col * 34 + row]           = acc[mt][nt][0];
                    rp[(col + 1) * 34 + row]     = acc[mt][nt][1];
                    rp[col * 34 + row + 8]       = acc[mt][nt][2];
                    rp[(col + 1) * 34 + row + 8] = acc[mt][nt][3];
                }
        }
        __syncthreads();

        // ---- LSTM elementwise update: thread = (unit u = wid, batch = lane)
        {
            const int u = wid, b = lane;
            float s[4];
#pragma unroll
            for (int g = 0; g < 4; g++) {
                float v = 0.f;
#pragma unroll
                for (int w2 = 0; w2 < 9; w2++)     // 8 partials + gates slot
                    v += red[w2 * 1088 + b * 34 + g * 8 + u];
                s[g] = v;
            }
            float si = 1.f / (1.f + expf(-s[0]));
            float sf = 1.f / (1.f + expf(-s[1]));
            float tg = tanhf(s[2]);
            float so = 1.f / (1.f + expf(-s[3]));
            c_reg = sf * c_reg + si * tg;
            float hn = so * tanhf(c_reg);

            int j = j0 + u;
            __nv_bfloat16 hh = __float2bfloat16(hn);
            __nv_bfloat16 hl = __float2bfloat16(hn - __bfloat162float(hh));
            hhout[b * H_ + j] = hh;
            hlout[b * H_ + j] = hl;
            if (aoh) {   // layer 0: feed layer-1 GEMM directly (bf16 hi/lo)
                size_t o = (size_t)t * B_ * H_ + b * H_ + j;
                aoh[o] = hh;
                aol[o] = hl;
            }
            if (t == T_ - 1) g_h0[b * H_ + j] = hn;
        }

        grid_barrier();   // h(t) globally visible before step t+1 stages it
    }
}

// ---------------- head: logits + log_softmax + NLL loss ----------------------
__global__ void head_k(const float* __restrict__ fcW, const float* __restrict__ fcb,
                       const int* __restrict__ labels, float* __restrict__ out,
                       int out_size) {
    __shared__ float lg[B_ * NL_];
    __shared__ float lsum[B_];
    int tid = threadIdx.x;

    if (tid < B_ * NL_) {
        int b = tid / NL_, n = tid % NL_;
        const float4* h4 = (const float4*)(g_h0 + b * H_);
        const float4* w4 = (const float4*)(fcW + n * H_);
        float s = 0.f;
        for (int k = 0; k < H_ / 4; k++) {
            float4 a = h4[k], w = w4[k];
            s += a.x * w.x + a.y * w.y + a.z * w.z + a.w * w.w;
        }
        lg[tid] = s + fcb[n];
    }
    __syncthreads();

    if (tid < B_) {
        float m = -1e30f;
        for (int n = 0; n < NL_; n++) m = fmaxf(m, lg[tid * NL_ + n]);
        float se = 0.f;
        for (int n = 0; n < NL_; n++) se += expf(lg[tid * NL_ + n] - m);
        float lse = m + logf(se);
        int lab = labels[tid];
        lsum[tid] = -(lg[tid * NL_ + lab] - lse);
    }
    __syncthreads();

    if (tid == 0) {
        float L = 0.f;
        for (int b = 0; b < B_; b++) L += lsum[b];
        L /= (float)B_;
        if (out_size >= 1 + B_ * NL_) {
            out[0] = L;
            for (int i = 0; i < B_ * NL_; i++) out[1 + i] = lg[i];
            for (int i = 1 + B_ * NL_; i < out_size; i++) out[i] = 0.f;
        } else if (out_size == B_ * NL_) {
            for (int i = 0; i < B_ * NL_; i++) out[i] = lg[i];
        } else if (out_size >= 1) {
            out[0] = L;
            for (int i = 1; i < out_size; i++) out[i] = 0.f;
        }
    }
}

// ---------------- launch -----------------------------------------------------
extern "C" void kernel_launch(void* const* d_in, const int* in_sizes, int n_in,
                              void* d_out, int out_size) {
    const int*   x      = (const int*)  d_in[0];
    const int*   labels = (const int*)  d_in[1];
    const float* emb    = (const float*)d_in[2];
    const float* Wih    = (const float*)d_in[3];   // [2, 4096, 1024]
    const float* Whh    = (const float*)d_in[4];   // [2, 4096, 1024]
    const float* bias   = (const float*)d_in[5];   // [2, 4096]
    const float* fcW    = (const float*)d_in[6];   // [5, 1024]
    const float* fcb    = (const float*)d_in[7];   // [5]

    cudaFuncSetAttribute(lstm_tc_k, cudaFuncAttributeMaxDynamicSharedMemorySize,
                         LSTM_SMEM);

    float *gates;
    __nv_bfloat16 *Ah, *Al, *Wh, *Wl, *WhH, *WhL;
    cudaGetSymbolAddress((void**)&gates, g_gates);
    cudaGetSymbolAddress((void**)&Ah, g_Ah);
    cudaGetSymbolAddress((void**)&Al, g_Al);
    cudaGetSymbolAddress((void**)&Wh, g_Wh);
    cudaGetSymbolAddress((void**)&Wl, g_Wl);
    cudaGetSymbolAddress((void**)&WhH, g_WhH);
    cudaGetSymbolAddress((void**)&WhL, g_WhL);

    // 0. split weights to bf16 hi/lo (input + recurrent)
    {
        int n4 = 2 * G4_ * H_ / 4;
        split_bf16_k<<<(n4 + 255) / 256, 256>>>(Wih, Wh, Wl, n4);
        split_bf16_k<<<(n4 + 255) / 256, 256>>>(Whh, WhH, WhL, n4);
    }
    // 1. embed -> g_Ah/g_Al directly (time-major [T, B, H], bf16 hi/lo)
    embed_k<<<T_ * B_, 256>>>(x, emb);

    for (int l = 0; l < 2; l++) {
        // 2. tensor-core input GEMM (A = g_Ah/g_Al; layer-0 LSTM refilled them)
        gemm_mma_k<<<dim3(G4_ / 128, (T_ * B_) / 128), 256>>>(
            Ah, Al, Wh + (size_t)l * G4_ * H_, Wl + (size_t)l * G4_ * H_,
            bias + (size_t)l * G4_, gates);
        // 3. tensor-core persistent recurrence; layer 0 writes h back into Ah/Al
        lstm_tc_k<<<NBLK, 256, LSTM_SMEM>>>(
            WhH + (size_t)l * G4_ * H_, WhL + (size_t)l * G4_ * H_,
            gates,
            (l == 0) ? Ah : ((__nv_bfloat16*)nullptr),
            (l == 0) ? Al : ((__nv_bfloat16*)nullptr));
    }

    // 4. head
    head_k<<<1, 256>>>(fcW, fcb, labels, (float*)d_out, out_size);
}

// round 16
// speedup vs baseline: 1.3172x; 1.0025x over previous
#include <cuda_runtime.h>
#include <cuda_bf16.h>
#include <math.h>
#include <stdint.h>

// Problem constants
static constexpr int T_   = 512;
static constexpr int B_   = 32;
static constexpr int H_   = 1024;
static constexpr int G4_  = 4096;   // 4*H
static constexpr int NL_  = 5;
static constexpr int NBLK = 128;    // persistent grid size

// ---------------- scratch (device globals; no allocations allowed) ----------
__device__ float g_gates[(size_t)T_ * B_ * G4_];
__device__ float g_h0[B_ * H_];                   // final h (for head)
__device__ unsigned int g_bar_count = 0;
__device__ unsigned int g_bar_gen   = 0;
// split-bf16 activations (layer input, time-major [T,B,H]); layer-0 LSTM
// overwrites these in place with its h outputs (input for layer-1 GEMM).
__device__ __nv_bfloat16 g_Ah[(size_t)T_ * B_ * H_];
__device__ __nv_bfloat16 g_Al[(size_t)T_ * B_ * H_];
// split-bf16 input-GEMM weights
__device__ __nv_bfloat16 g_Wh[(size_t)2 * G4_ * H_];
__device__ __nv_bfloat16 g_Wl[(size_t)2 * G4_ * H_];
// split-bf16 recurrent weights
__device__ __nv_bfloat16 g_WhH[(size_t)2 * G4_ * H_];
__device__ __nv_bfloat16 g_WhL[(size_t)2 * G4_ * H_];
// double-buffered bf16 hidden state (hi/lo), [B][H] row-major
__device__ __nv_bfloat16 g_hhA[B_ * H_];
__device__ __nv_bfloat16 g_hlA[B_ * H_];
__device__ __nv_bfloat16 g_hhB[B_ * H_];
__device__ __nv_bfloat16 g_hlB[B_ * H_];

__device__ __forceinline__ uint32_t smem_u32(const void* p) {
    uint32_t a;
    asm("{ .reg .u64 t; cvta.to.shared.u64 t, %1; cvt.u32.u64 %0, t; }" : "=r"(a) : "l"(p));
    return a;
}
__device__ __forceinline__ void mma16816(float* c, const uint32_t* a, const uint32_t* b) {
    asm volatile(
        "mma.sync.aligned.m16n8k16.row.col.f32.bf16.bf16.f32 "
        "{%0,%1,%2,%3}, {%4,%5,%6,%7}, {%8,%9}, {%0,%1,%2,%3};"
        : "+f"(c[0]), "+f"(c[1]), "+f"(c[2]), "+f"(c[3])
        : "r"(a[0]), "r"(a[1]), "r"(a[2]), "r"(a[3]), "r"(b[0]), "r"(b[1]));
}
__device__ __forceinline__ void ldmx4(uint32_t* r, uint32_t addr) {
    asm volatile("ldmatrix.sync.aligned.m8n8.x4.shared.b16 {%0,%1,%2,%3}, [%4];"
                 : "=r"(r[0]), "=r"(r[1]), "=r"(r[2]), "=r"(r[3]) : "r"(addr));
}
__device__ __forceinline__ void ldmx2(uint32_t* r, uint32_t addr) {
    asm volatile("ldmatrix.sync.aligned.m8n8.x2.shared.b16 {%0,%1}, [%2];"
                 : "=r"(r[0]), "=r"(r[1]) : "r"(addr));
}
__device__ __forceinline__ void cp_async16(uint32_t saddr, const void* g) {
    asm volatile("cp.async.cg.shared.global [%0], [%1], 16;" :: "r"(saddr), "l"(g) : "memory");
}

// ---------------- embedding gather + bf16 hi/lo split (fused) ---------------
__global__ void embed_k(const int* __restrict__ x, const float* __restrict__ emb) {
    int tb = blockIdx.x;            // tb = t*B + b  (time-major)
    int t = tb / B_;
    int b = tb % B_;
    int tok = x[b * T_ + t];
    float4 v = ((const float4*)(emb + (size_t)tok * H_))[threadIdx.x];
    __nv_bfloat16 h0 = __float2bfloat16(v.x);
    __nv_bfloat16 h1 = __float2bfloat16(v.y);
    __nv_bfloat16 h2 = __float2bfloat16(v.z);
    __nv_bfloat16 h3 = __float2bfloat16(v.w);
    __nv_bfloat16 l0 = __float2bfloat16(v.x - __bfloat162float(h0));
    __nv_bfloat16 l1 = __float2bfloat16(v.y - __bfloat162float(h1));
    __nv_bfloat16 l2 = __float2bfloat16(v.z - __bfloat162float(h2));
    __nv_bfloat16 l3 = __float2bfloat16(v.w - __bfloat162float(h3));
    __nv_bfloat162* hp = (__nv_bfloat162*)(g_Ah + (size_t)tb * H_) + threadIdx.x * 2;
    __nv_bfloat162* lp = (__nv_bfloat162*)(g_Al + (size_t)tb * H_) + threadIdx.x * 2;
    hp[0] = __nv_bfloat162(h0, h1); hp[1] = __nv_bfloat162(h2, h3);
    lp[0] = __nv_bfloat162(l0, l1); lp[1] = __nv_bfloat162(l2, l3);
}

// ---------------- fp32 -> bf16 (hi, lo) split (weights only) ----------------
__global__ void split_bf16_k(const float* __restrict__ src,
                             __nv_bfloat16* __restrict__ hi,
                             __nv_bfloat16* __restrict__ lo, int n4) {
    int i = blockIdx.x * blockDim.x + threadIdx.x;
    if (i >= n4) return;
    float4 v = ((const float4*)src)[i];
    __nv_bfloat16 h0 = __float2bfloat16(v.x);
    __nv_bfloat16 h1 = __float2bfloat16(v.y);
    __nv_bfloat16 h2 = __float2bfloat16(v.z);
    __nv_bfloat16 h3 = __float2bfloat16(v.w);
    __nv_bfloat16 l0 = __float2bfloat16(v.x - __bfloat162float(h0));
    __nv_bfloat16 l1 = __float2bfloat16(v.y - __bfloat162float(h1));
    __nv_bfloat16 l2 = __float2bfloat16(v.z - __bfloat162float(h2));
    __nv_bfloat16 l3 = __float2bfloat16(v.w - __bfloat162float(h3));
    __nv_bfloat162* hp = (__nv_bfloat162*)hi;
    __nv_bfloat162* lp = (__nv_bfloat162*)lo;
    hp[2 * i]     = __nv_bfloat162(h0, h1);
    hp[2 * i + 1] = __nv_bfloat162(h2, h3);
    lp[2 * i]     = __nv_bfloat162(l0, l1);
    lp[2 * i + 1] = __nv_bfloat162(l2, l3);
}

// ---------------- mma.sync split-bf16 input GEMM (double-buffered) ----------
// Block tile 128x128, BK=64, 8 warps (2m x 4n). Two-stage dynamic smem,
// ONE __syncthreads per k-iter. 64 KB dynamic smem; 2 CTAs/SM (126 regs).
static constexpr int GEMM_SMEM = 65536;

__global__ __launch_bounds__(256)
void gemm_mma_k(const __nv_bfloat16* __restrict__ Ah, const __nv_bfloat16* __restrict__ Al,
                const __nv_bfloat16* __restrict__ Wh, const __nv_bfloat16* __restrict__ Wl,
                const float* __restrict__ bias, float* __restrict__ C) {
    extern __shared__ char gsm[];

    const int tid  = threadIdx.x;
    const int warp = tid >> 5;
    const int lane = tid & 31;
    const int wm = warp >> 2;
    const int wn = warp & 3;
    const int m0 = blockIdx.y * 128;
    const int n0 = blockIdx.x * 128;

    const __nv_bfloat16* srcA[3] = {Ah, Ah, Al};
    const __nv_bfloat16* srcW[3] = {Wh, Wl, Wh};

    int rowL[4], uL[4], dstL[4];
#pragma unroll
    for (int i = 0; i < 4; i++) {
        int idx = i * 256 + tid;
        rowL[i] = idx >> 3;
        uL[i]   = idx & 7;
        dstL[i] = (rowL[i] * 64 + ((uL[i] ^ (rowL[i] & 7)) << 3)) * 2;   // bytes
    }

    float acc[4][4][4];
#pragma unroll
    for (int mt = 0; mt < 4; mt++)
#pragma unroll
        for (int nt = 0; nt < 4; nt++)
#pragma unroll
            for (int q = 0; q < 4; q++) acc[mt][nt][q] = 0.f;

    int lrowA[4], lrowB[4];
#pragma unroll
    for (int mt = 0; mt < 4; mt++) lrowA[mt] = wm * 64 + mt * 16 + (lane & 15);
#pragma unroll
    for (int nt = 0; nt < 4; nt++) lrowB[nt] = wn * 32 + nt * 8 + (lane & 7);
    const uint32_t sbase = smem_u32(gsm);

    float4 pa[4], pw[4];
#pragma unroll
    for (int i = 0; i < 4; i++) {
        pa[i] = *(const float4*)(srcA[0] + (size_t)(m0 + rowL[i]) * H_ + uL[i] * 8);
        pw[i] = *(const float4*)(srcW[0] + (size_t)(n0 + rowL[i]) * H_ + uL[i] * 8);
    }
    // fill stage 0
#pragma unroll
    for (int i = 0; i < 4; i++) {
        *(float4*)(gsm + dstL[i])         = pa[i];
        *(float4*)(gsm + 32768 + dstL[i]) = pw[i];
    }
    __syncthreads();

    for (int it = 0; it < 48; it++) {
        const int cur = it & 1;
        const int nxt = cur ^ 1;
        const uint32_t a_base = sbase + cur * 16384;
        const uint32_t w_base = sbase + 32768 + cur * 16384;

        // prefetch next tile into registers (flies over the MMAs)
        if (it + 1 < 48) {
            int p2 = (it + 1) >> 4;
            int kcol2 = ((it + 1) & 15) * 64;
#pragma unroll
            for (int i = 0; i < 4; i++) {
                pa[i] = *(const float4*)(srcA[p2] + (size_t)(m0 + rowL[i]) * H_ + kcol2 + uL[i] * 8);
                pw[i] = *(const float4*)(srcW[p2] + (size_t)(n0 + rowL[i]) * H_ + kcol2 + uL[i] * 8);
            }
        }

#pragma unroll
        for (int ks = 0; ks < 4; ks++) {
            uint32_t af[4][4], bf[4][2];
            int ua = ks * 2 + (lane >> 4);
#pragma unroll
            for (int mt = 0; mt < 4; mt++)
                ldmx4(af[mt], a_base + (uint32_t)(lrowA[mt] * 128 + ((ua ^ (lrowA[mt] & 7)) << 4)));
            int ub = ks * 2 + ((lane >> 3) & 1);
#pragma unroll
            for (int nt = 0; nt < 4; nt++)
                ldmx2(bf[nt], w_base + (uint32_t)(lrowB[nt] * 128 + ((ub ^ (lrowB[nt] & 7)) << 4)));
#pragma unroll
            for (int mt = 0; mt < 4; mt++)
#pragma unroll
                for (int nt = 0; nt < 4; nt++)
                    mma16816(acc[mt][nt], af[mt], bf[nt]);
        }

        // store prefetched tile into the other stage
        if (it + 1 < 48) {
#pragma unroll
            for (int i = 0; i < 4; i++) {
                *(float4*)(gsm + nxt * 16384 + dstL[i])         = pa[i];
                *(float4*)(gsm + 32768 + nxt * 16384 + dstL[i]) = pw[i];
            }
        }
        __syncthreads();
    }

    const int qr = lane >> 2;
    const int qc = (lane & 3) * 2;
#pragma unroll
    for (int mt = 0; mt < 4; mt++) {
        int rm = m0 + wm * 64 + mt * 16 + qr;
#pragma unroll
        for (int nt = 0; nt < 4; nt++) {
            int cb = n0 + wn * 32 + nt * 8 + qc;
            float b0 = bias[cb], b1 = bias[cb + 1];
            *(float2*)(C + (size_t)rm * G4_ + cb) =
                make_float2(acc[mt][nt][0] + b0, acc[mt][nt][1] + b1);
            *(float2*)(C + (size_t)(rm + 8) * G4_ + cb) =
                make_float2(acc[mt][nt][2] + b0, acc[mt][nt][3] + b1);
        }
    }
}

// ---------------- flat grid barrier (tighter poll) ---------------------------
__device__ __forceinline__ void grid_barrier() {
    __syncthreads();
    if (threadIdx.x == 0) {
        __threadfence();
        unsigned g = *((volatile unsigned*)&g_bar_gen);
        unsigned arrived = atomicAdd(&g_bar_count, 1u) + 1u;
        if (arrived == (unsigned)NBLK) {
            g_bar_count = 0;
            __threadfence();
            atomicAdd(&g_bar_gen, 1u);
        } else {
            while (*((volatile unsigned*)&g_bar_gen) == g) { __nanosleep(32); }
        }
    }
    __syncthreads();
}

// ---------------- tensor-core persistent recurrence --------------------------
// 128 blocks x 256 threads (8 warps); block owns 8 hidden units = 32 gate rows.
// Whh hi AND lo fragments live in registers (loop-invariant). Per step each
// WARP stages only ITS OWN h K-slice (chunks 2*wid, 2*wid+1) via cp.async and
// waits only its own group. B fragments loaded with ldmatrix.x4 (nt pairs).
// Gates stage into red[8]; all warps write red[wid]; ONE __syncthreads/step.
static constexpr int HH_OFF  = 0;         // 65536 B
static constexpr int HL_OFF  = 65536;     // 65536 B
static constexpr int RED_OFF = 131072;    // 9 x 32cols x 34pad x 4B = 39168 B
static constexpr int LSTM_SMEM = 170240;

__global__ __launch_bounds__(256, 1)
void lstm_tc_k(const __nv_bfloat16* __restrict__ WhH,
               const __nv_bfloat16* __restrict__ WhL,
               const float* __restrict__ gates,
               __nv_bfloat16* __restrict__ aoh,   // layer-0: write h as bf16 hi
               __nv_bfloat16* __restrict__ aol) { // layer-0: write h as bf16 lo
    extern __shared__ char smem[];
    float* red = (float*)(smem + RED_OFF);
    const uint32_t sbase   = smem_u32(smem);
    const uint32_t hh_base = sbase + HH_OFF;
    const uint32_t hl_base = sbase + HL_OFF;

    const int tid  = threadIdx.x;
    const int wid  = tid >> 5;
    const int lane = tid & 31;
    const int j0   = blockIdx.x * 8;

    // zero the global bf16 h buffers (exact cover: 128 blk * 256 thr = 32768)
    {
        int i = blockIdx.x * 256 + tid;
        g_hhA[i] = __nv_bfloat16(0.f); g_hlA[i] = __nv_bfloat16(0.f);
        g_hhB[i] = __nv_bfloat16(0.f); g_hlB[i] = __nv_bfloat16(0.f);
    }

    // ---- prologue: stage Whh hi -> HH, lo -> HL, then load fragments -------
    for (int idx = tid; idx < 32 * 128; idx += 256) {
        int r = idx >> 7, f = idx & 127;
        int grow = (r >> 3) * H_ + j0 + (r & 7);
        int dst = (f >> 3) * 4096 + r * 128 + (((f & 7) ^ (r & 7)) << 4);
        *(float4*)(smem + HH_OFF + dst) = *(const float4*)(WhH + (size_t)grow * H_ + f * 8);
        *(float4*)(smem + HL_OFF + dst) = *(const float4*)(WhL + (size_t)grow * H_ + f * 8);
    }
    __syncthreads();

    const int lrA0 = (lane & 15);
    const int kselA = lane >> 4;

    // Whh hi AND lo fragments in registers: [mt][ks][4] x2 = 128 regs
    uint32_t wh[2][8][4], wl[2][8][4];
#pragma unroll
    for (int mt = 0; mt < 2; mt++)
#pragma unroll
        for (int ks = 0; ks < 8; ks++) {
            int c  = wid * 2 + (ks >> 2);
            int ua = (ks & 3) * 2 + kselA;
            int lr = mt * 16 + lrA0;
            uint32_t off = (uint32_t)(c * 4096 + lr * 128 + ((ua ^ (lr & 7)) << 4));
            ldmx4(wh[mt][ks], hh_base + off);
            ldmx4(wl[mt][ks], hl_base + off);
        }
    grid_barrier();   // h zeroing visible; HH/HL smem free for h staging

    // B-side ldmatrix.x4 lane geometry: 4 matrices = (nt pair) x (k halves)
    const int tselB  = (lane >> 4) & 1;   // which nt of the pair
    const int khalfB = (lane >> 3) & 1;   // which k-half
    const int lrB0   = lane & 7;

    float c_reg = 0.f;   // cell state for (unit=wid, batch=lane)

    for (int t = 0; t < T_; t++) {
        const __nv_bfloat16* hhin = (t & 1) ? g_hhB : g_hhA;
        const __nv_bfloat16* hlin = (t & 1) ? g_hlB : g_hlA;
        __nv_bfloat16* hhout = (t & 1) ? g_hhA : g_hhB;
        __nv_bfloat16* hlout = (t & 1) ? g_hlA : g_hlB;
        const float* gates_t = gates + (size_t)t * B_ * G4_;

        // ---- warp-local h staging: this warp's chunks 2*wid, 2*wid+1 -------
        {
            const char* hh8 = (const char*)hhin;
            const char* hl8 = (const char*)hlin;
#pragma unroll
            for (int k = 0; k < 8; k++) {
                int idx = k * 32 + lane;        // 0..255 within a chunk
                int r  = idx >> 3;              // batch row 0..31
                int fc = idx & 7;               // float4 within (row, chunk)
                uint32_t sw = (uint32_t)(r * 128 + ((fc ^ (r & 7)) << 4));
#pragma unroll
                for (int cc = 0; cc < 2; cc++) {
                    int c = wid * 2 + cc;
                    uint32_t doff = (uint32_t)(c * 4096) + sw;
                    size_t goff = (size_t)((r * 128 + c * 8 + fc) * 16);
                    cp_async16(hh_base + doff, hh8 + goff);
                    cp_async16(hl_base + doff, hl8 + goff);
                }
            }
        }
        // stage gate pre-activations into red[8] (independent of cp.async)
        {
            int b = tid >> 3, q = tid & 7, g = q >> 1, half = q & 1;
            float4 v = *(const float4*)(gates_t + (size_t)b * G4_ + g * H_ + j0 + half * 4);
            float* rp = red + 8 * 1088 + b * 34 + g * 8 + half * 4;
            rp[0] = v.x; rp[1] = v.y; rp[2] = v.z; rp[3] = v.w;
        }
        asm volatile("cp.async.commit_group;\n\tcp.async.wait_group 0;" ::: "memory");
        __syncwarp();

        // ---- MMA phase: weights from registers, own-warp h from smem -------
        float acc[2][4][4];
#pragma unroll
        for (int mt = 0; mt < 2; mt++)
#pragma unroll
            for (int nt = 0; nt < 4; nt++)
#pragma unroll
                for (int q = 0; q < 4; q++) acc[mt][nt][q] = 0.f;

#pragma unroll
        for (int ks = 0; ks < 8; ks++) {
            int c  = wid * 2 + (ks >> 2);
            int klo = (ks & 3) * 2;
            uint32_t bh[4][2], bl[4][2];
#pragma unroll
            for (int nt2 = 0; nt2 < 4; nt2 += 2) {
                int lr = (nt2 + tselB) * 8 + lrB0;
                int ub = klo + khalfB;
                uint32_t off = (uint32_t)(c * 4096 + lr * 128 + ((ub ^ (lr & 7)) << 4));
                uint32_t r4[4];
                ldmx4(r4, hh_base + off);
                bh[nt2][0] = r4[0]; bh[nt2][1] = r4[1];
                bh[nt2 + 1][0] = r4[2]; bh[nt2 + 1][1] = r4[3];
                ldmx4(r4, hl_base + off);
                bl[nt2][0] = r4[0]; bl[nt2][1] = r4[1];
                bl[nt2 + 1][0] = r4[2]; bl[nt2 + 1][1] = r4[3];
            }
#pragma unroll
            for (int mt = 0; mt < 2; mt++)
#pragma unroll
                for (int nt = 0; nt < 4; nt++) {
                    mma16816(acc[mt][nt], wh[mt][ks], bh[nt]);   // wh*hh
                    mma16816(acc[mt][nt], wh[mt][ks], bl[nt]);   // wh*hl
                    mma16816(acc[mt][nt], wl[mt][ks], bh[nt]);   // wl*hh
                }
        }

        // ---- write own partial slot red[wid] (no special cases) ------------
        {
            const int qr = lane >> 2;
            const int qc = (lane & 3) * 2;
            float* rp = red + wid * 1088;
#pragma unroll
            for (int mt = 0; mt < 2; mt++)
#pragma unroll
                for (int nt = 0; nt < 4; nt++) {
                    int row = mt * 16 + qr;
                    int col = nt * 8 + qc;
                    rp[col * 34 + row]           = acc[mt][nt][0];
                    rp[(col + 1) * 34 + row]     = acc[mt][nt][1];
                    rp[col * 34 + row + 8]       = acc[mt][nt][2];
                    rp[(col + 1) * 34 + row + 8] = acc[mt][nt][3];
                }
        }
        __syncthreads();

        // ---- LSTM elementwise update: thread = (unit u = wid, batch = lane)
        {
            const int u = wid, b = lane;
            float s[4];
#pragma unroll
            for (int g = 0; g < 4; g++) {
                float v = 0.f;
#pragma unroll
                for (int w2 = 0; w2 < 9; w2++)     // 8 partials + gates slot
                    v += red[w2 * 1088 + b * 34 + g * 8 + u];
                s[g] = v;
            }
            float si = 1.f / (1.f + expf(-s[0]));
            float sf = 1.f / (1.f + expf(-s[1]));
            float tg = tanhf(s[2]);
            float so = 1.f / (1.f + expf(-s[3]));
            c_reg = sf * c_reg + si * tg;
            float hn = so * tanhf(c_reg);

            int j = j0 + u;
            __nv_bfloat16 hh = __float2bfloat16(hn);
            __nv_bfloat16 hl = __float2bfloat16(hn - __bfloat162float(hh));
            hhout[b * H_ + j] = hh;
            hlout[b * H_ + j] = hl;
            if (aoh) {   // layer 0: feed layer-1 GEMM directly (bf16 hi/lo)
                size_t o = (size_t)t * B_ * H_ + b * H_ + j;
                aoh[o] = hh;
                aol[o] = hl;
            }
            if (t == T_ - 1) g_h0[b * H_ + j] = hn;
        }

        grid_barrier();   // h(t) globally visible before step t+1 stages it
    }
}

// ---------------- head: logits + log_softmax + NLL loss ----------------------
__global__ void head_k(const float* __restrict__ fcW, const float* __restrict__ fcb,
                       const int* __restrict__ labels, float* __restrict__ out,
                       int out_size) {
    __shared__ float lg[B_ * NL_];
    __shared__ float lsum[B_];
    int tid = threadIdx.x;

    if (tid < B_ * NL_) {
        int b = tid / NL_, n = tid % NL_;
        const float4* h4 = (const float4*)(g_h0 + b * H_);
        const float4* w4 = (const float4*)(fcW + n * H_);
        float s = 0.f;
        for (int k = 0; k < H_ / 4; k++) {
            float4 a = h4[k], w = w4[k];
            s += a.x * w.x + a.y * w.y + a.z * w.z + a.w * w.w;
        }
        lg[tid] = s + fcb[n];
    }
    __syncthreads();

    if (tid < B_) {
        float m = -1e30f;
        for (int n = 0; n < NL_; n++) m = fmaxf(m, lg[tid * NL_ + n]);
        float se = 0.f;
        for (int n = 0; n < NL_; n++) se += expf(lg[tid * NL_ + n] - m);
        float lse = m + logf(se);
        int lab = labels[tid];
        lsum[tid] = -(lg[tid * NL_ + lab] - lse);
    }
    __syncthreads();

    if (tid == 0) {
        float L = 0.f;
        for (int b = 0; b < B_; b++) L += lsum[b];
        L /= (float)B_;
        if (out_size >= 1 + B_ * NL_) {
            out[0] = L;
            for (int i = 0; i < B_ * NL_; i++) out[1 + i] = lg[i];
            for (int i = 1 + B_ * NL_; i < out_size; i++) out[i] = 0.f;
        } else if (out_size == B_ * NL_) {
            for (int i = 0; i < B_ * NL_; i++) out[i] = lg[i];
        } else if (out_size >= 1) {
            out[0] = L;
            for (int i = 1; i < out_size; i++) out[i] = 0.f;
        }
    }
}

// ---------------- launch -----------------------------------------------------
extern "C" void kernel_launch(void* const* d_in, const int* in_sizes, int n_in,
                              void* d_out, int out_size) {
    const int*   x      = (const int*)  d_in[0];
    const int*   labels = (const int*)  d_in[1];
    const float* emb    = (const float*)d_in[2];
    const float* Wih    = (const float*)d_in[3];   // [2, 4096, 1024]
    const float* Whh    = (const float*)d_in[4];   // [2, 4096, 1024]
    const float* bias   = (const float*)d_in[5];   // [2, 4096]
    const float* fcW    = (const float*)d_in[6];   // [5, 1024]
    const float* fcb    = (const float*)d_in[7];   // [5]

    cudaFuncSetAttribute(lstm_tc_k, cudaFuncAttributeMaxDynamicSharedMemorySize,
                         LSTM_SMEM);
    cudaFuncSetAttribute(gemm_mma_k, cudaFuncAttributeMaxDynamicSharedMemorySize,
                         GEMM_SMEM);

    float *gates;
    __nv_bfloat16 *Ah, *Al, *Wh, *Wl, *WhH, *WhL;
    cudaGetSymbolAddress((void**)&gates, g_gates);
    cudaGetSymbolAddress((void**)&Ah, g_Ah);
    cudaGetSymbolAddress((void**)&Al, g_Al);
    cudaGetSymbolAddress((void**)&Wh, g_Wh);
    cudaGetSymbolAddress((void**)&Wl, g_Wl);
    cudaGetSymbolAddress((void**)&WhH, g_WhH);
    cudaGetSymbolAddress((void**)&WhL, g_WhL);

    // 0. split weights to bf16 hi/lo (input + recurrent)
    {
        int n4 = 2 * G4_ * H_ / 4;
        split_bf16_k<<<(n4 + 255) / 256, 256>>>(Wih, Wh, Wl, n4);
        split_bf16_k<<<(n4 + 255) / 256, 256>>>(Whh, WhH, WhL, n4);
    }
    // 1. embed -> g_Ah/g_Al directly (time-major [T, B, H], bf16 hi/lo)
    embed_k<<<T_ * B_, 256>>>(x, emb);

    for (int l = 0; l < 2; l++) {
        // 2. tensor-core input GEMM (A = g_Ah/g_Al; layer-0 LSTM refilled them)
        gemm_mma_k<<<dim3(G4_ / 128, (T_ * B_) / 128), 256, GEMM_SMEM>>>(
            Ah, Al, Wh + (size_t)l * G4_ * H_, Wl + (size_t)l * G4_ * H_,
            bias + (size_t)l * G4_, gates);
        // 3. tensor-core persistent recurrence; layer 0 writes h back into Ah/Al
        lstm_tc_k<<<NBLK, 256, LSTM_SMEM>>>(
            WhH + (size_t)l * G4_ * H_, WhL + (size_t)l * G4_ * H_,
            gates,
            (l == 0) ? Ah : ((__nv_bfloat16*)nullptr),
            (l == 0) ? Al : ((__nv_bfloat16*)nullptr));
    }

    // 4. head
    head_k<<<1, 256>>>(fcW, fcb, labels, (float*)d_out, out_size);
}

// round 17
// speedup vs baseline: 1.3509x; 1.0256x over previous
#include <cuda_runtime.h>
#include <cuda_bf16.h>
#include <math.h>
#include <stdint.h>

// Problem constants
static constexpr int T_   = 512;
static constexpr int B_   = 32;
static constexpr int H_   = 1024;
static constexpr int G4_  = 4096;   // 4*H
static constexpr int NL_  = 5;
static constexpr int NBLK = 128;    // persistent grid size

// ---------------- scratch (device globals; no allocations allowed) ----------
__device__ float g_gates[(size_t)T_ * B_ * G4_];
__device__ float g_h0[B_ * H_];                   // final h (for head)
__device__ unsigned int g_bar_count = 0;
__device__ unsigned int g_bar_gen   = 0;
// split-bf16 activations (layer input, time-major [T,B,H]); layer-0 LSTM
// overwrites these in place with its h outputs (input for layer-1 GEMM).
__device__ __nv_bfloat16 g_Ah[(size_t)T_ * B_ * H_];
__device__ __nv_bfloat16 g_Al[(size_t)T_ * B_ * H_];
// split-bf16 input-GEMM weights
__device__ __nv_bfloat16 g_Wh[(size_t)2 * G4_ * H_];
__device__ __nv_bfloat16 g_Wl[(size_t)2 * G4_ * H_];
// split-bf16 recurrent weights
__device__ __nv_bfloat16 g_WhH[(size_t)2 * G4_ * H_];
__device__ __nv_bfloat16 g_WhL[(size_t)2 * G4_ * H_];
// double-buffered bf16 hidden state (hi/lo), [B][H] row-major
__device__ __nv_bfloat16 g_hhA[B_ * H_];
__device__ __nv_bfloat16 g_hlA[B_ * H_];
__device__ __nv_bfloat16 g_hhB[B_ * H_];
__device__ __nv_bfloat16 g_hlB[B_ * H_];

__device__ __forceinline__ uint32_t smem_u32(const void* p) {
    uint32_t a;
    asm("{ .reg .u64 t; cvta.to.shared.u64 t, %1; cvt.u32.u64 %0, t; }" : "=r"(a) : "l"(p));
    return a;
}
__device__ __forceinline__ void mma16816(float* c, const uint32_t* a, const uint32_t* b) {
    asm volatile(
        "mma.sync.aligned.m16n8k16.row.col.f32.bf16.bf16.f32 "
        "{%0,%1,%2,%3}, {%4,%5,%6,%7}, {%8,%9}, {%0,%1,%2,%3};"
        : "+f"(c[0]), "+f"(c[1]), "+f"(c[2]), "+f"(c[3])
        : "r"(a[0]), "r"(a[1]), "r"(a[2]), "r"(a[3]), "r"(b[0]), "r"(b[1]));
}
__device__ __forceinline__ void ldmx4(uint32_t* r, uint32_t addr) {
    asm volatile("ldmatrix.sync.aligned.m8n8.x4.shared.b16 {%0,%1,%2,%3}, [%4];"
                 : "=r"(r[0]), "=r"(r[1]), "=r"(r[2]), "=r"(r[3]) : "r"(addr));
}
__device__ __forceinline__ void ldmx2(uint32_t* r, uint32_t addr) {
    asm volatile("ldmatrix.sync.aligned.m8n8.x2.shared.b16 {%0,%1}, [%2];"
                 : "=r"(r[0]), "=r"(r[1]) : "r"(addr));
}
__device__ __forceinline__ void cp_async16(uint32_t saddr, const void* g) {
    asm volatile("cp.async.cg.shared.global [%0], [%1], 16;" :: "r"(saddr), "l"(g) : "memory");
}
// saturation-robust fast sigmoid / tanh (MUFU-based; rel err ~1e-6)
__device__ __forceinline__ float fast_sigmoid(float x) {
    return __fdividef(1.f, 1.f + __expf(-x));
}
__device__ __forceinline__ float fast_tanh(float x) {
    return 1.f - __fdividef(2.f, __expf(2.f * x) + 1.f);
}

// ---------------- embedding gather + bf16 hi/lo split (fused) ---------------
__global__ void embed_k(const int* __restrict__ x, const float* __restrict__ emb) {
    int tb = blockIdx.x;            // tb = t*B + b  (time-major)
    int t = tb / B_;
    int b = tb % B_;
    int tok = x[b * T_ + t];
    float4 v = ((const float4*)(emb + (size_t)tok * H_))[threadIdx.x];
    __nv_bfloat16 h0 = __float2bfloat16(v.x);
    __nv_bfloat16 h1 = __float2bfloat16(v.y);
    __nv_bfloat16 h2 = __float2bfloat16(v.z);
    __nv_bfloat16 h3 = __float2bfloat16(v.w);
    __nv_bfloat16 l0 = __float2bfloat16(v.x - __bfloat162float(h0));
    __nv_bfloat16 l1 = __float2bfloat16(v.y - __bfloat162float(h1));
    __nv_bfloat16 l2 = __float2bfloat16(v.z - __bfloat162float(h2));
    __nv_bfloat16 l3 = __float2bfloat16(v.w - __bfloat162float(h3));
    __nv_bfloat162* hp = (__nv_bfloat162*)(g_Ah + (size_t)tb * H_) + threadIdx.x * 2;
    __nv_bfloat162* lp = (__nv_bfloat162*)(g_Al + (size_t)tb * H_) + threadIdx.x * 2;
    hp[0] = __nv_bfloat162(h0, h1); hp[1] = __nv_bfloat162(h2, h3);
    lp[0] = __nv_bfloat162(l0, l1); lp[1] = __nv_bfloat162(l2, l3);
}

// ---------------- fp32 -> bf16 (hi, lo) split (weights only) ----------------
__global__ void split_bf16_k(const float* __restrict__ src,
                             __nv_bfloat16* __restrict__ hi,
                             __nv_bfloat16* __restrict__ lo, int n4) {
    int i = blockIdx.x * blockDim.x + threadIdx.x;
    if (i >= n4) return;
    float4 v = ((const float4*)src)[i];
    __nv_bfloat16 h0 = __float2bfloat16(v.x);
    __nv_bfloat16 h1 = __float2bfloat16(v.y);
    __nv_bfloat16 h2 = __float2bfloat16(v.z);
    __nv_bfloat16 h3 = __float2bfloat16(v.w);
    __nv_bfloat16 l0 = __float2bfloat16(v.x - __bfloat162float(h0));
    __nv_bfloat16 l1 = __float2bfloat16(v.y - __bfloat162float(h1));
    __nv_bfloat16 l2 = __float2bfloat16(v.z - __bfloat162float(h2));
    __nv_bfloat16 l3 = __float2bfloat16(v.w - __bfloat162float(h3));
    __nv_bfloat162* hp = (__nv_bfloat162*)hi;
    __nv_bfloat162* lp = (__nv_bfloat162*)lo;
    hp[2 * i]     = __nv_bfloat162(h0, h1);
    hp[2 * i + 1] = __nv_bfloat162(h2, h3);
    lp[2 * i]     = __nv_bfloat162(l0, l1);
    lp[2 * i + 1] = __nv_bfloat162(l2, l3);
}

// ---------------- mma.sync split-bf16 input GEMM (double-buffered) ----------
static constexpr int GEMM_SMEM = 65536;

__global__ __launch_bounds__(256)
void gemm_mma_k(const __nv_bfloat16* __restrict__ Ah, const __nv_bfloat16* __restrict__ Al,
                const __nv_bfloat16* __restrict__ Wh, const __nv_bfloat16* __restrict__ Wl,
                const float* __restrict__ bias, float* __restrict__ C) {
    extern __shared__ char gsm[];

    const int tid  = threadIdx.x;
    const int warp = tid >> 5;
    const int lane = tid & 31;
    const int wm = warp >> 2;
    const int wn = warp & 3;
    const int m0 = blockIdx.y * 128;
    const int n0 = blockIdx.x * 128;

    const __nv_bfloat16* srcA[3] = {Ah, Ah, Al};
    const __nv_bfloat16* srcW[3] = {Wh, Wl, Wh};

    int rowL[4], uL[4], dstL[4];
#pragma unroll
    for (int i = 0; i < 4; i++) {
        int idx = i * 256 + tid;
        rowL[i] = idx >> 3;
        uL[i]   = idx & 7;
        dstL[i] = (rowL[i] * 64 + ((uL[i] ^ (rowL[i] & 7)) << 3)) * 2;   // bytes
    }

    float acc[4][4][4];
#pragma unroll
    for (int mt = 0; mt < 4; mt++)
#pragma unroll
        for (int nt = 0; nt < 4; nt++)
#pragma unroll
            for (int q = 0; q < 4; q++) acc[mt][nt][q] = 0.f;

    int lrowA[4], lrowB[4];
#pragma unroll
    for (int mt = 0; mt < 4; mt++) lrowA[mt] = wm * 64 + mt * 16 + (lane & 15);
#pragma unroll
    for (int nt = 0; nt < 4; nt++) lrowB[nt] = wn * 32 + nt * 8 + (lane & 7);
    const uint32_t sbase = smem_u32(gsm);

    float4 pa[4], pw[4];
#pragma unroll
    for (int i = 0; i < 4; i++) {
        pa[i] = *(const float4*)(srcA[0] + (size_t)(m0 + rowL[i]) * H_ + uL[i] * 8);
        pw[i] = *(const float4*)(srcW[0] + (size_t)(n0 + rowL[i]) * H_ + uL[i] * 8);
    }
#pragma unroll
    for (int i = 0; i < 4; i++) {
        *(float4*)(gsm + dstL[i])         = pa[i];
        *(float4*)(gsm + 32768 + dstL[i]) = pw[i];
    }
    __syncthreads();

    for (int it = 0; it < 48; it++) {
        const int cur = it & 1;
        const int nxt = cur ^ 1;
        const uint32_t a_base = sbase + cur * 16384;
        const uint32_t w_base = sbase + 32768 + cur * 16384;

        if (it + 1 < 48) {
            int p2 = (it + 1) >> 4;
            int kcol2 = ((it + 1) & 15) * 64;
#pragma unroll
            for (int i = 0; i < 4; i++) {
                pa[i] = *(const float4*)(srcA[p2] + (size_t)(m0 + rowL[i]) * H_ + kcol2 + uL[i] * 8);
                pw[i] = *(const float4*)(srcW[p2] + (size_t)(n0 + rowL[i]) * H_ + kcol2 + uL[i] * 8);
            }
        }

#pragma unroll
        for (int ks = 0; ks < 4; ks++) {
            uint32_t af[4][4], bf[4][2];
            int ua = ks * 2 + (lane >> 4);
#pragma unroll
            for (int mt = 0; mt < 4; mt++)
                ldmx4(af[mt], a_base + (uint32_t)(lrowA[mt] * 128 + ((ua ^ (lrowA[mt] & 7)) << 4)));
            int ub = ks * 2 + ((lane >> 3) & 1);
#pragma unroll
            for (int nt = 0; nt < 4; nt++)
                ldmx2(bf[nt], w_base + (uint32_t)(lrowB[nt] * 128 + ((ub ^ (lrowB[nt] & 7)) << 4)));
#pragma unroll
            for (int mt = 0; mt < 4; mt++)
#pragma unroll
                for (int nt = 0; nt < 4; nt++)
                    mma16816(acc[mt][nt], af[mt], bf[nt]);
        }

        if (it + 1 < 48) {
#pragma unroll
            for (int i = 0; i < 4; i++) {
                *(float4*)(gsm + nxt * 16384 + dstL[i])         = pa[i];
                *(float4*)(gsm + 32768 + nxt * 16384 + dstL[i]) = pw[i];
            }
        }
        __syncthreads();
    }

    const int qr = lane >> 2;
    const int qc = (lane & 3) * 2;
#pragma unroll
    for (int mt = 0; mt < 4; mt++) {
        int rm = m0 + wm * 64 + mt * 16 + qr;
#pragma unroll
        for (int nt = 0; nt < 4; nt++) {
            int cb = n0 + wn * 32 + nt * 8 + qc;
            float b0 = bias[cb], b1 = bias[cb + 1];
            *(float2*)(C + (size_t)rm * G4_ + cb) =
                make_float2(acc[mt][nt][0] + b0, acc[mt][nt][1] + b1);
            *(float2*)(C + (size_t)(rm + 8) * G4_ + cb) =
                make_float2(acc[mt][nt][2] + b0, acc[mt][nt][3] + b1);
        }
    }
}

// ---------------- flat grid barrier: PURE SPIN (no __nanosleep) --------------
// __nanosleep wakeup quantum can be ~0.5-1us; across 1024 barriers that is
// milliseconds. Only thread 0 of each block polls -> 128 loads to one L2
// line, ~4cyc each at the LTS: busy-spin is cheap and detection latency is
// one L2 round trip (~260cyc).
__device__ __forceinline__ void grid_barrier() {
    __syncthreads();
    if (threadIdx.x == 0) {
        __threadfence();
        unsigned g = *((volatile unsigned*)&g_bar_gen);
        unsigned arrived = atomicAdd(&g_bar_count, 1u) + 1u;
        if (arrived == (unsigned)NBLK) {
            g_bar_count = 0;
            __threadfence();
            atomicAdd(&g_bar_gen, 1u);
        } else {
            while (*((volatile unsigned*)&g_bar_gen) == g) { }
        }
    }
    __syncthreads();
}

// ---------------- tensor-core persistent recurrence --------------------------
static constexpr int HH_OFF  = 0;         // 65536 B
static constexpr int HL_OFF  = 65536;     // 65536 B
static constexpr int RED_OFF = 131072;    // 9 x 32cols x 34pad x 4B = 39168 B
static constexpr int LSTM_SMEM = 170240;

__global__ __launch_bounds__(256, 1)
void lstm_tc_k(const __nv_bfloat16* __restrict__ WhH,
               const __nv_bfloat16* __restrict__ WhL,
               const float* __restrict__ gates,
               __nv_bfloat16* __restrict__ aoh,   // layer-0: write h as bf16 hi
               __nv_bfloat16* __restrict__ aol) { // layer-0: write h as bf16 lo
    extern __shared__ char smem[];
    float* red = (float*)(smem + RED_OFF);
    const uint32_t sbase   = smem_u32(smem);
    const uint32_t hh_base = sbase + HH_OFF;
    const uint32_t hl_base = sbase + HL_OFF;

    const int tid  = threadIdx.x;
    const int wid  = tid >> 5;
    const int lane = tid & 31;
    const int j0   = blockIdx.x * 8;

    // zero the global bf16 h buffers (exact cover: 128 blk * 256 thr = 32768)
    {
        int i = blockIdx.x * 256 + tid;
        g_hhA[i] = __nv_bfloat16(0.f); g_hlA[i] = __nv_bfloat16(0.f);
        g_hhB[i] = __nv_bfloat16(0.f); g_hlB[i] = __nv_bfloat16(0.f);
    }

    // ---- prologue: stage Whh hi -> HH, lo -> HL, then load fragments -------
    for (int idx = tid; idx < 32 * 128; idx += 256) {
        int r = idx >> 7, f = idx & 127;
        int grow = (r >> 3) * H_ + j0 + (r & 7);
        int dst = (f >> 3) * 4096 + r * 128 + (((f & 7) ^ (r & 7)) << 4);
        *(float4*)(smem + HH_OFF + dst) = *(const float4*)(WhH + (size_t)grow * H_ + f * 8);
        *(float4*)(smem + HL_OFF + dst) = *(const float4*)(WhL + (size_t)grow * H_ + f * 8);
    }
    __syncthreads();

    const int lrA0 = (lane & 15);
    const int kselA = lane >> 4;

    // Whh hi AND lo fragments in registers: [mt][ks][4] x2 = 128 regs
    uint32_t wh[2][8][4], wl[2][8][4];
#pragma unroll
    for (int mt = 0; mt < 2; mt++)
#pragma unroll
        for (int ks = 0; ks < 8; ks++) {
            int c  = wid * 2 + (ks >> 2);
            int ua = (ks & 3) * 2 + kselA;
            int lr = mt * 16 + lrA0;
            uint32_t off = (uint32_t)(c * 4096 + lr * 128 + ((ua ^ (lr & 7)) << 4));
            ldmx4(wh[mt][ks], hh_base + off);
            ldmx4(wl[mt][ks], hl_base + off);
        }
    grid_barrier();   // h zeroing visible; HH/HL smem free for h staging

    // B-side ldmatrix.x4 lane geometry: 4 matrices = (nt pair) x (k halves)
    const int tselB  = (lane >> 4) & 1;
    const int khalfB = (lane >> 3) & 1;
    const int lrB0   = lane & 7;

    float c_reg = 0.f;   // cell state for (unit=wid, batch=lane)

    for (int t = 0; t < T_; t++) {
        const __nv_bfloat16* hhin = (t & 1) ? g_hhB : g_hhA;
        const __nv_bfloat16* hlin = (t & 1) ? g_hlB : g_hlA;
        __nv_bfloat16* hhout = (t & 1) ? g_hhA : g_hhB;
        __nv_bfloat16* hlout = (t & 1) ? g_hlA : g_hlB;
        const float* gates_t = gates + (size_t)t * B_ * G4_;

        // ---- warp-local h staging: this warp's chunks 2*wid, 2*wid+1 -------
        {
            const char* hh8 = (const char*)hhin;
            const char* hl8 = (const char*)hlin;
#pragma unroll
            for (int k = 0; k < 8; k++) {
                int idx = k * 32 + lane;        // 0..255 within a chunk
                int r  = idx >> 3;              // batch row 0..31
                int fc = idx & 7;               // float4 within (row, chunk)
                uint32_t sw = (uint32_t)(r * 128 + ((fc ^ (r & 7)) << 4));
#pragma unroll
                for (int cc = 0; cc < 2; cc++) {
                    int c = wid * 2 + cc;
                    uint32_t doff = (uint32_t)(c * 4096) + sw;
                    size_t goff = (size_t)((r * 128 + c * 8 + fc) * 16);
                    cp_async16(hh_base + doff, hh8 + goff);
                    cp_async16(hl_base + doff, hl8 + goff);
                }
            }
        }
        // stage gate pre-activations into red[8] (independent of cp.async)
        {
            int b = tid >> 3, q = tid & 7, g = q >> 1, half = q & 1;
            float4 v = *(const float4*)(gates_t + (size_t)b * G4_ + g * H_ + j0 + half * 4);
            float* rp = red + 8 * 1088 + b * 34 + g * 8 + half * 4;
            rp[0] = v.x; rp[1] = v.y; rp[2] = v.z; rp[3] = v.w;
        }
        asm volatile("cp.async.commit_group;\n\tcp.async.wait_group 0;" ::: "memory");
        __syncwarp();

        // ---- MMA phase: weights from registers, own-warp h from smem -------
        float acc[2][4][4];
#pragma unroll
        for (int mt = 0; mt < 2; mt++)
#pragma unroll
            for (int nt = 0; nt < 4; nt++)
#pragma unroll
                for (int q = 0; q < 4; q++) acc[mt][nt][q] = 0.f;

#pragma unroll
        for (int ks = 0; ks < 8; ks++) {
            int c  = wid * 2 + (ks >> 2);
            int klo = (ks & 3) * 2;
            uint32_t bh[4][2], bl[4][2];
#pragma unroll
            for (int nt2 = 0; nt2 < 4; nt2 += 2) {
                int lr = (nt2 + tselB) * 8 + lrB0;
                int ub = klo + khalfB;
                uint32_t off = (uint32_t)(c * 4096 + lr * 128 + ((ub ^ (lr & 7)) << 4));
                uint32_t r4[4];
                ldmx4(r4, hh_base + off);
                bh[nt2][0] = r4[0]; bh[nt2][1] = r4[1];
                bh[nt2 + 1][0] = r4[2]; bh[nt2 + 1][1] = r4[3];
                ldmx4(r4, hl_base + off);
                bl[nt2][0] = r4[0]; bl[nt2][1] = r4[1];
                bl[nt2 + 1][0] = r4[2]; bl[nt2 + 1][1] = r4[3];
            }
#pragma unroll
            for (int mt = 0; mt < 2; mt++)
#pragma unroll
                for (int nt = 0; nt < 4; nt++) {
                    mma16816(acc[mt][nt], wh[mt][ks], bh[nt]);   // wh*hh
                    mma16816(acc[mt][nt], wh[mt][ks], bl[nt]);   // wh*hl
                    mma16816(acc[mt][nt], wl[mt][ks], bh[nt]);   // wl*hh
                }
        }

        // ---- write own partial slot red[wid] ------------------------------
        {
            const int qr = lane >> 2;
            const int qc = (lane & 3) * 2;
            float* rp = red + wid * 1088;
#pragma unroll
            for (int mt = 0; mt < 2; mt++)
#pragma unroll
                for (int nt = 0; nt < 4; nt++) {
                    int row = mt * 16 + qr;
                    int col = nt * 8 + qc;
                    rp[col * 34 + row]           = acc[mt][nt][0];
                    rp[(col + 1) * 34 + row]     = acc[mt][nt][1];
                    rp[col * 34 + row + 8]       = acc[mt][nt][2];
                    rp[(col + 1) * 34 + row + 8] = acc[mt][nt][3];
                }
        }
        __syncthreads();

        // ---- LSTM elementwise update: thread = (unit u = wid, batch = lane)
        {
            const int u = wid, b = lane;
            float s[4];
#pragma unroll
            for (int g = 0; g < 4; g++) {
                float v = 0.f;
#pragma unroll
                for (int w2 = 0; w2 < 9; w2++)     // 8 partials + gates slot
                    v += red[w2 * 1088 + b * 34 + g * 8 + u];
                s[g] = v;
            }
            float si = fast_sigmoid(s[0]);
            float sf = fast_sigmoid(s[1]);
            float tg = fast_tanh(s[2]);
            float so = fast_sigmoid(s[3]);
            c_reg = sf * c_reg + si * tg;
            float hn = so * fast_tanh(c_reg);

            int j = j0 + u;
            __nv_bfloat16 hh = __float2bfloat16(hn);
            __nv_bfloat16 hl = __float2bfloat16(hn - __bfloat162float(hh));
            hhout[b * H_ + j] = hh;
            hlout[b * H_ + j] = hl;
            if (aoh) {   // layer 0: feed layer-1 GEMM directly (bf16 hi/lo)
                size_t o = (size_t)t * B_ * H_ + b * H_ + j;
                aoh[o] = hh;
                aol[o] = hl;
            }
            if (t == T_ - 1) g_h0[b * H_ + j] = hn;
        }

        grid_barrier();   // h(t) globally visible before step t+1 stages it
    }
}

// ---------------- head: logits + log_softmax + NLL loss ----------------------
__global__ void head_k(const float* __restrict__ fcW, const float* __restrict__ fcb,
                       const int* __restrict__ labels, float* __restrict__ out,
                       int out_size) {
    __shared__ float lg[B_ * NL_];
    __shared__ float lsum[B_];
    int tid = threadIdx.x;

    if (tid < B_ * NL_) {
        int b = tid / NL_, n = tid % NL_;
        const float4* h4 = (const float4*)(g_h0 + b * H_);
        const float4* w4 = (const float4*)(fcW + n * H_);
        float s = 0.f;
        for (int k = 0; k < H_ / 4; k++) {
            float4 a = h4[k], w = w4[k];
            s += a.x * w.x + a.y * w.y + a.z * w.z + a.w * w.w;
        }
        lg[tid] = s + fcb[n];
    }
    __syncthreads();

    if (tid < B_) {
        float m = -1e30f;
        for (int n = 0; n < NL_; n++) m = fmaxf(m, lg[tid * NL_ + n]);
        float se = 0.f;
        for (int n = 0; n < NL_; n++) se += expf(lg[tid * NL_ + n] - m);
        float lse = m + logf(se);
        int lab = labels[tid];
        lsum[tid] = -(lg[tid * NL_ + lab] - lse);
    }
    __syncthreads();

    if (tid == 0) {
        float L = 0.f;
        for (int b = 0; b < B_; b++) L += lsum[b];
        L /= (float)B_;
        if (out_size >= 1 + B_ * NL_) {
            out[0] = L;
            for (int i = 0; i < B_ * NL_; i++) out[1 + i] = lg[i];
            for (int i = 1 + B_ * NL_; i < out_size; i++) out[i] = 0.f;
        } else if (out_size == B_ * NL_) {
            for (int i = 0; i < B_ * NL_; i++) out[i] = lg[i];
        } else if (out_size >= 1) {
            out[0] = L;
            for (int i = 1; i < out_size; i++) out[i] = 0.f;
        }
    }
}

// ---------------- launch -----------------------------------------------------
extern "C" void kernel_launch(void* const* d_in, const int* in_sizes, int n_in,
                              void* d_out, int out_size) {
    const int*   x      = (const int*)  d_in[0];
    const int*   labels = (const int*)  d_in[1];
    const float* emb    = (const float*)d_in[2];
    const float* Wih    = (const float*)d_in[3];   // [2, 4096, 1024]
    const float* Whh    = (const float*)d_in[4];   // [2, 4096, 1024]
    const float* bias   = (const float*)d_in[5];   // [2, 4096]
    const float* fcW    = (const float*)d_in[6];   // [5, 1024]
    const float* fcb    = (const float*)d_in[7];   // [5]

    cudaFuncSetAttribute(lstm_tc_k, cudaFuncAttributeMaxDynamicSharedMemorySize,
                         LSTM_SMEM);
    cudaFuncSetAttribute(gemm_mma_k, cudaFuncAttributeMaxDynamicSharedMemorySize,
                         GEMM_SMEM);

    float *gates;
    __nv_bfloat16 *Ah, *Al, *Wh, *Wl, *WhH, *WhL;
    cudaGetSymbolAddress((void**)&gates, g_gates);
    cudaGetSymbolAddress((void**)&Ah, g_Ah);
    cudaGetSymbolAddress((void**)&Al, g_Al);
    cudaGetSymbolAddress((void**)&Wh, g_Wh);
    cudaGetSymbolAddress((void**)&Wl, g_Wl);
    cudaGetSymbolAddress((void**)&WhH, g_WhH);
    cudaGetSymbolAddress((void**)&WhL, g_WhL);

    // 0. split weights to bf16 hi/lo (input + recurrent)
    {
        int n4 = 2 * G4_ * H_ / 4;
        split_bf16_k<<<(n4 + 255) / 256, 256>>>(Wih, Wh, Wl, n4);
        split_bf16_k<<<(n4 + 255) / 256, 256>>>(Whh, WhH, WhL, n4);
    }
    // 1. embed -> g_Ah/g_Al directly (time-major [T, B, H], bf16 hi/lo)
    embed_k<<<T_ * B_, 256>>>(x, emb);

    for (int l = 0; l < 2; l++) {
        // 2. tensor-core input GEMM (A = g_Ah/g_Al; layer-0 LSTM refilled them)
        gemm_mma_k<<<dim3(G4_ / 128, (T_ * B_) / 128), 256, GEMM_SMEM>>>(
            Ah, Al, Wh + (size_t)l * G4_ * H_, Wl + (size_t)l * G4_ * H_,
            bias + (size_t)l * G4_, gates);
        // 3. tensor-core persistent recurrence; layer 0 writes h back into Ah/Al
        lstm_tc_k<<<NBLK, 256, LSTM_SMEM>>>(
            WhH + (size_t)l * G4_ * H_, WhL + (size_t)l * G4_ * H_,
            gates,
            (l == 0) ? Ah : ((__nv_bfloat16*)nullptr),
            (l == 0) ? Al : ((__nv_bfloat16*)nullptr));
    }

    // 4. head
    head_k<<<1, 256>>>(fcW, fcb, labels, (float*)d_out, out_size);
}